// round 7
// baseline (speedup 1.0000x reference)
#include <cuda_runtime.h>
#include <cstdint>

// ---------------------------------------------------------------------------
// PCT position-embedding + 4 offset-attention SA layers. B=8, C=256, D=64,
// N=2048. tf32 mma.sync, operands pre-rounded rna. Block tile 128x256,
// warp tile 64x64 (L1-traffic-optimized), 4-stage cp.async ring.
// ---------------------------------------------------------------------------

#define B_   8
#define C_   256
#define D_   64
#define N_   2048

__device__ float g_pos [B_ * C_ * N_];
__device__ float g_h0  [B_ * C_ * N_];
__device__ float g_h1  [B_ * C_ * N_];
__device__ float g_hp  [B_ * C_ * N_];
__device__ float g_xrnd[B_ * C_ * N_];
__device__ float g_q   [B_ * D_ * N_];
__device__ float g_qT  [B_ * N_ * D_];
__device__ float g_val [B_ * C_ * N_];
__device__ float g_d   [B_ * C_ * N_];
__device__ float g_att [(long long)B_ * N_ * N_];
__device__ float g_wts [655360];

__device__ __forceinline__ float rna_tf32(float x) {
    uint32_t u;
    asm("cvt.rna.tf32.f32 %0, %1;" : "=r"(u) : "f"(x));
    return __uint_as_float(u);
}
__device__ __forceinline__ uint32_t smem_u32(const void* p) {
    return (uint32_t)__cvta_generic_to_shared(p);
}

// ---------------------------------------------------------------------------
// warp-tile compute: 64x64 warp tile, 2 ks x (4 ldmatrix + 16 LDS + 32 mma)
// A row stride 20 floats, B row stride 264 floats.
// ---------------------------------------------------------------------------
__device__ __forceinline__ void compute_tile(
    const float* __restrict__ Asb, const float* __restrict__ Bsb,
    float acc[4][8][4], int lane, int wm0, int wn0, int g, int tg)
{
#pragma unroll
    for (int ks = 0; ks < 2; ks++) {
        uint32_t a[4][4];
#pragma unroll
        for (int mt = 0; mt < 4; mt++) {
            const float* pa = Asb + (wm0 + mt * 16 + (lane & 15)) * 20
                            + ks * 8 + (lane >> 4) * 4;
            uint32_t ad = smem_u32(pa);
            asm volatile("ldmatrix.sync.aligned.m8n8.x4.shared.b16 {%0,%1,%2,%3}, [%4];"
                : "=r"(a[mt][0]), "=r"(a[mt][1]), "=r"(a[mt][2]), "=r"(a[mt][3])
                : "r"(ad));
        }
        uint32_t bf[8][2];
#pragma unroll
        for (int nt = 0; nt < 8; nt++) {
            bf[nt][0] = __float_as_uint(Bsb[(ks * 8 + tg    ) * 264 + wn0 + nt * 8 + g]);
            bf[nt][1] = __float_as_uint(Bsb[(ks * 8 + tg + 4) * 264 + wn0 + nt * 8 + g]);
        }
#pragma unroll
        for (int mt = 0; mt < 4; mt++)
#pragma unroll
            for (int nt = 0; nt < 8; nt++) {
                asm volatile(
                    "mma.sync.aligned.m16n8k8.row.col.f32.tf32.tf32.f32 "
                    "{%0,%1,%2,%3}, {%4,%5,%6,%7}, {%8,%9}, {%0,%1,%2,%3};"
                    : "+f"(acc[mt][nt][0]), "+f"(acc[mt][nt][1]),
                      "+f"(acc[mt][nt][2]), "+f"(acc[mt][nt][3])
                    : "r"(a[mt][0]), "r"(a[mt][1]), "r"(a[mt][2]), "r"(a[mt][3]),
                      "r"(bf[nt][0]), "r"(bf[nt][1]));
            }
    }
}

// ---------------------------------------------------------------------------
// prep kernel: rounds all weights + x, computes pos.
// ---------------------------------------------------------------------------
#define SEG_W1   65536L
#define SEG_QV   327680L
#define SEG_WT   262144L
#define SEG_X    ((long)B_ * C_ * N_)
#define PREP_TOT (SEG_W1 + SEG_QV + SEG_WT + SEG_X + SEG_X)

__global__ void prep_kernel(const float* __restrict__ conv1_w,
                            const float* __restrict__ Wqk,
                            const float* __restrict__ Wv,
                            const float* __restrict__ Wt,
                            const float* __restrict__ x,
                            const float* __restrict__ convpos,
                            const float* __restrict__ xyz)
{
    long i = (long)blockIdx.x * 256 + threadIdx.x;
    if (i >= PREP_TOT) return;
    if (i < SEG_W1) {
        g_wts[i] = rna_tf32(conv1_w[i]);
    } else if (i < SEG_W1 + SEG_QV) {
        long j = i - SEG_W1;
        int layer = (int)(j / 81920);
        long o = j % 81920;
        float v = (o < 16384) ? Wqk[(long)layer * 16384 + o]
                              : Wv[(long)layer * 65536 + (o - 16384)];
        g_wts[i] = rna_tf32(v);
    } else if (i < SEG_W1 + SEG_QV + SEG_WT) {
        g_wts[i] = rna_tf32(Wt[i - SEG_W1 - SEG_QV]);
    } else if (i < SEG_W1 + SEG_QV + SEG_WT + SEG_X) {
        long j = i - SEG_W1 - SEG_QV - SEG_WT;
        g_xrnd[j] = rna_tf32(x[j]);
    } else {
        long j = i - SEG_W1 - SEG_QV - SEG_WT - SEG_X;
        int n = (int)(j % N_);
        int c = (int)((j / N_) % C_);
        int b = (int)(j / ((long)C_ * N_));
        const float* pp = xyz + ((long)b * N_ + n) * 3;
        g_pos[j] = convpos[c * 3 + 0] * pp[0] + convpos[c * 3 + 1] * pp[1]
                 + convpos[c * 3 + 2] * pp[2];
    }
}

// ---------------------------------------------------------------------------
// tf32 GEMM, block tile 128x256, 4-stage cp.async ring, 1 barrier/stage.
// ---------------------------------------------------------------------------
enum { EPI_BN_RELU = 0, EPI_QVAL = 1, EPI_PLAIN = 2, EPI_COLSCALE = 3,
       EPI_T_UPDATE = 4 };

#define TG_STAGES   4
#define TG_AS_STR   (128 * 20)              // 2560 floats per A stage
#define TG_BS_STR   (16 * 264)              // 4224 floats per B stage
#define TG_B_OFF    (TG_STAGES * TG_AS_STR)
#define TG_CS_OFF   (TG_B_OFF + TG_STAGES * TG_BS_STR)
#define TG_CSB_OFF  (TG_CS_OFF + 16 * 256)
#define TG_SMEM     ((TG_CSB_OFF + 256) * 4)

template <int EPI>
__global__ void __launch_bounds__(256)
tgemm(const float* __restrict__ A, long aStride, int M, int K,
      const float* __restrict__ Bm, long bStride,
      float* __restrict__ Cm, long cStride,
      const float* __restrict__ bias,
      const float* __restrict__ bng, const float* __restrict__ bnb,
      const float* __restrict__ bnm, const float* __restrict__ bnv,
      const float* __restrict__ hres, long hresStride,
      const float* __restrict__ posB,
      float* __restrict__ hpOut,
      float* __restrict__ out2, long out2Stride,
      float* __restrict__ qB, float* __restrict__ qTB)
{
    extern __shared__ float smd[];
    float* AsBase = smd;
    float* BsBase = smd + TG_B_OFF;
    float (*csred)[256] = reinterpret_cast<float(*)[256]>(smd + TG_CS_OFF);
    float* csb = smd + TG_CSB_OFF;

    const int bz = blockIdx.z;
    const float* Ab = A + (long)bz * aStride;
    const float* Bb = Bm + (long)bz * bStride;

    const int m0 = blockIdx.y * 128;
    const int n0 = blockIdx.x * 256;
    const int t  = threadIdx.x;
    const int lane = t & 31;
    const int w    = t >> 5;
    const int g  = lane >> 2, tg = lane & 3;
    const int wm0 = (w >> 2) * 64, wn0 = (w & 3) * 64;

    float acc[4][8][4];
#pragma unroll
    for (int i = 0; i < 4; i++)
#pragma unroll
        for (int j = 0; j < 8; j++)
#pragma unroll
            for (int k = 0; k < 4; k++) acc[i][j][k] = 0.f;

    float csum[4][4];
    if (EPI == EPI_COLSCALE) {
#pragma unroll
        for (int qd = 0; qd < 4; qd++)
#pragma unroll
            for (int j = 0; j < 4; j++) csum[qd][j] = 0.f;
    }

    const int aR0 = t >> 2,  aC = (t & 3) * 4;   // A: 128 rows x 4 float4
    const int nStages = K >> 4;

    // prologue: first min(3, nStages) stages
    const int npro = (nStages < TG_STAGES - 1) ? nStages : (TG_STAGES - 1);
    for (int s = 0; s < npro; s++) {
        const int k0 = s * 16;
        float* As = AsBase + s * TG_AS_STR;
        float* Bs = BsBase + s * TG_BS_STR;
#pragma unroll
        for (int h = 0; h < 2; h++) {
            int row = aR0 + h * 64;
            if (m0 + row < M) {
                uint32_t dst = smem_u32(As + row * 20 + aC);
                const float* src = Ab + (long)(m0 + row) * K + k0 + aC;
                asm volatile("cp.async.cg.shared.global [%0], [%1], 16;" :: "r"(dst), "l"(src));
            }
        }
#pragma unroll
        for (int qd = 0; qd < 4; qd++) {
            int idx = t + 256 * qd;
            int row = idx >> 6, cg = (idx & 63) * 4;
            uint32_t dst = smem_u32(Bs + row * 264 + cg);
            const float* src = Bb + (long)(k0 + row) * N_ + n0 + cg;
            asm volatile("cp.async.cg.shared.global [%0], [%1], 16;" :: "r"(dst), "l"(src));
        }
        asm volatile("cp.async.commit_group;");
    }

    for (int s = 0; s < nStages; s++) {
        const int buf = s & (TG_STAGES - 1);
        asm volatile("cp.async.wait_group %0;" :: "n"(TG_STAGES - 2));
        __syncthreads();

        const int sn = s + TG_STAGES - 1;
        if (sn < nStages) {
            const int k0 = sn * 16, nb = sn & (TG_STAGES - 1);
            float* As = AsBase + nb * TG_AS_STR;
            float* Bs = BsBase + nb * TG_BS_STR;
#pragma unroll
            for (int h = 0; h < 2; h++) {
                int row = aR0 + h * 64;
                if (m0 + row < M) {
                    uint32_t dst = smem_u32(As + row * 20 + aC);
                    const float* src = Ab + (long)(m0 + row) * K + k0 + aC;
                    asm volatile("cp.async.cg.shared.global [%0], [%1], 16;" :: "r"(dst), "l"(src));
                }
            }
#pragma unroll
            for (int qd = 0; qd < 4; qd++) {
                int idx = t + 256 * qd;
                int row = idx >> 6, cg = (idx & 63) * 4;
                uint32_t dst = smem_u32(Bs + row * 264 + cg);
                const float* src = Bb + (long)(k0 + row) * N_ + n0 + cg;
                asm volatile("cp.async.cg.shared.global [%0], [%1], 16;" :: "r"(dst), "l"(src));
            }
        }
        asm volatile("cp.async.commit_group;");

        const float* AsC = AsBase + buf * TG_AS_STR;
        const float* BsC = BsBase + buf * TG_BS_STR;

        if (EPI == EPI_COLSCALE) {
#pragma unroll
            for (int qd = 0; qd < 4; qd++) {
                int idx = t + 256 * qd;
                int row = idx >> 6, cg = (idx & 63) * 4;
                const float4 v = *reinterpret_cast<const float4*>(BsC + row * 264 + cg);
                csum[qd][0] += v.x; csum[qd][1] += v.y;
                csum[qd][2] += v.z; csum[qd][3] += v.w;
            }
        }
        compute_tile(AsC, BsC, acc, lane, wm0, wn0, g, tg);
    }

    if (EPI == EPI_COLSCALE) {
        __syncthreads();
#pragma unroll
        for (int qd = 0; qd < 4; qd++) {
            int idx = t + 256 * qd;
            int row = idx >> 6, cg = (idx & 63) * 4;
            csred[row][cg + 0] = csum[qd][0];
            csred[row][cg + 1] = csum[qd][1];
            csred[row][cg + 2] = csum[qd][2];
            csred[row][cg + 3] = csum[qd][3];
        }
        __syncthreads();
        {
            float ssum = 0.f;
#pragma unroll
            for (int r = 0; r < 16; r++) ssum += csred[r][t];
            csb[t] = 1.f / (1e-9f + ssum);
        }
        __syncthreads();
    }

    float* Cb = Cm + (long)bz * cStride;
#pragma unroll
    for (int mt = 0; mt < 4; mt++) {
#pragma unroll
        for (int half = 0; half < 2; half++) {
            const int r = m0 + wm0 + mt * 16 + g + half * 8;
            if (r >= M) continue;

            float sc = 1.f, sh = 0.f, bsv = 0.f;
            if (EPI == EPI_BN_RELU || EPI == EPI_T_UPDATE) {
                float inv = rsqrtf(bnv[r] + 1e-5f);
                sc = bng[r] * inv; sh = bnb[r] - bnm[r] * sc;
            }
            if (EPI == EPI_T_UPDATE) bsv = bias[r];
            if (EPI == EPI_QVAL && r >= 64) bsv = bias[r - 64];

#pragma unroll
            for (int nt = 0; nt < 8; nt++) {
                const int cb = n0 + wn0 + nt * 8 + 2 * tg;
                float v0 = acc[mt][nt][half * 2 + 0];
                float v1 = acc[mt][nt][half * 2 + 1];
                long rowoff = (long)r * N_ + cb;

                if (EPI == EPI_BN_RELU) {
                    v0 = fmaxf(fmaf(v0, sc, sh), 0.f);
                    v1 = fmaxf(fmaf(v1, sc, sh), 0.f);
                    *reinterpret_cast<float2*>(Cb + rowoff) = make_float2(v0, v1);
                    const float* pb = posB + (long)bz * hresStride;
                    float2 p2 = *reinterpret_cast<const float2*>(pb + rowoff);
                    float* hbp = hpOut + (long)bz * hresStride;
                    *reinterpret_cast<float2*>(hbp + rowoff) =
                        make_float2(rna_tf32(v0 + p2.x), rna_tf32(v1 + p2.y));
                } else if (EPI == EPI_QVAL) {
                    if (r < 64) {
                        float q0 = rna_tf32(v0), q1 = rna_tf32(v1);
                        float* qb = qB + (long)bz * ((long)D_ * N_);
                        *reinterpret_cast<float2*>(qb + (long)r * N_ + cb) = make_float2(q0, q1);
                        float* qt = qTB + (long)bz * ((long)N_ * D_);
                        qt[(long)cb * D_ + r]       = q0;
                        qt[(long)(cb + 1) * D_ + r] = q1;
                    } else {
                        long vo = (long)(r - 64) * N_ + cb;
                        *reinterpret_cast<float2*>(Cb + vo) =
                            make_float2(rna_tf32(v0 + bsv), rna_tf32(v1 + bsv));
                    }
                } else if (EPI == EPI_PLAIN) {
                    *reinterpret_cast<float2*>(Cb + rowoff) = make_float2(v0, v1);
                } else if (EPI == EPI_COLSCALE) {
                    float i0 = csb[cb - n0], i1 = csb[cb - n0 + 1];
                    const float* hb = hres + (long)bz * hresStride;
                    float2 h2 = *reinterpret_cast<const float2*>(hb + rowoff);
                    *reinterpret_cast<float2*>(Cb + rowoff) =
                        make_float2(rna_tf32(h2.x - v0 * i0), rna_tf32(h2.y - v1 * i1));
                } else { // EPI_T_UPDATE
                    v0 = fmaxf(fmaf(v0 + bsv, sc, sh), 0.f);
                    v1 = fmaxf(fmaf(v1 + bsv, sc, sh), 0.f);
                    const float* hb = hres + (long)bz * hresStride;
                    float2 h2 = *reinterpret_cast<const float2*>(hb + rowoff);
                    float o0 = v0 + h2.x, o1 = v1 + h2.y;
                    *reinterpret_cast<float2*>(Cb + rowoff) = make_float2(o0, o1);
                    float* ob = out2 + (long)bz * out2Stride;
                    *reinterpret_cast<float2*>(ob + rowoff) = make_float2(o0, o1);
                    const float* pb = posB + (long)bz * hresStride;
                    float2 p2 = *reinterpret_cast<const float2*>(pb + rowoff);
                    float* hb2 = hpOut + (long)bz * hresStride;
                    *reinterpret_cast<float2*>(hb2 + rowoff) =
                        make_float2(rna_tf32(o0 + p2.x), rna_tf32(o1 + p2.y));
                }
            }
        }
    }
}

// ---------------------------------------------------------------------------
// Row softmax (in place), float4 + __expf, writes tf32-rounded values.
// ---------------------------------------------------------------------------
__global__ void __launch_bounds__(256)
softmax_kernel(float* __restrict__ E)
{
    long row = blockIdx.x;
    float4* r = reinterpret_cast<float4*>(E + row * (long)N_);
    const int t = threadIdx.x;

    float4 va = r[t];
    float4 vb = r[t + 256];
    float mx = fmaxf(fmaxf(fmaxf(va.x, va.y), fmaxf(va.z, va.w)),
                     fmaxf(fmaxf(vb.x, vb.y), fmaxf(vb.z, vb.w)));

    __shared__ float red[8];
#pragma unroll
    for (int o = 16; o > 0; o >>= 1) mx = fmaxf(mx, __shfl_xor_sync(0xffffffffu, mx, o));
    if ((t & 31) == 0) red[t >> 5] = mx;
    __syncthreads();
    float bm = red[0];
#pragma unroll
    for (int w = 1; w < 8; w++) bm = fmaxf(bm, red[w]);
    __syncthreads();

    va.x = __expf(va.x - bm); va.y = __expf(va.y - bm);
    va.z = __expf(va.z - bm); va.w = __expf(va.w - bm);
    vb.x = __expf(vb.x - bm); vb.y = __expf(vb.y - bm);
    vb.z = __expf(vb.z - bm); vb.w = __expf(vb.w - bm);
    float sum = va.x + va.y + va.z + va.w + vb.x + vb.y + vb.z + vb.w;
#pragma unroll
    for (int o = 16; o > 0; o >>= 1) sum += __shfl_xor_sync(0xffffffffu, sum, o);
    if ((t & 31) == 0) red[t >> 5] = sum;
    __syncthreads();
    float tot = 0.f;
#pragma unroll
    for (int w = 0; w < 8; w++) tot += red[w];

    float inv = 1.f / tot;
    va.x = rna_tf32(va.x * inv); va.y = rna_tf32(va.y * inv);
    va.z = rna_tf32(va.z * inv); va.w = rna_tf32(va.w * inv);
    vb.x = rna_tf32(vb.x * inv); vb.y = rna_tf32(vb.y * inv);
    vb.z = rna_tf32(vb.z * inv); vb.w = rna_tf32(vb.w * inv);
    r[t] = va;
    r[t + 256] = vb;
}

// ---------------------------------------------------------------------------
extern "C" void kernel_launch(void* const* d_in, const int* in_sizes, int n_in,
                              void* d_out, int out_size)
{
    (void)in_sizes; (void)n_in; (void)out_size;

    const float* x       = (const float*)d_in[0];
    const float* xyz     = (const float*)d_in[1];
    const float* conv1_w = (const float*)d_in[2];
    const float* convpos = (const float*)d_in[3];
    const float* bn1_g   = (const float*)d_in[4];
    const float* bn1_b   = (const float*)d_in[5];
    const float* bn1_m   = (const float*)d_in[6];
    const float* bn1_v   = (const float*)d_in[7];
    const float* Wqk     = (const float*)d_in[8];
    const float* Wv      = (const float*)d_in[9];
    const float* bv      = (const float*)d_in[10];
    const float* Wt      = (const float*)d_in[11];
    const float* bt      = (const float*)d_in[12];
    const float* bng     = (const float*)d_in[13];
    const float* bnb     = (const float*)d_in[14];
    const float* bnm     = (const float*)d_in[15];
    const float* bnv     = (const float*)d_in[16];
    float* out = (float*)d_out;

    float *pos, *h0, *h1, *hp, *xrnd, *q, *qT, *val, *dbuf, *att, *wts;
    cudaGetSymbolAddress((void**)&pos,  g_pos);
    cudaGetSymbolAddress((void**)&h0,   g_h0);
    cudaGetSymbolAddress((void**)&h1,   g_h1);
    cudaGetSymbolAddress((void**)&hp,   g_hp);
    cudaGetSymbolAddress((void**)&xrnd, g_xrnd);
    cudaGetSymbolAddress((void**)&q,    g_q);
    cudaGetSymbolAddress((void**)&qT,   g_qT);
    cudaGetSymbolAddress((void**)&val,  g_val);
    cudaGetSymbolAddress((void**)&dbuf, g_d);
    cudaGetSymbolAddress((void**)&att,  g_att);
    cudaGetSymbolAddress((void**)&wts,  g_wts);

    cudaFuncSetAttribute(tgemm<EPI_BN_RELU>,  cudaFuncAttributeMaxDynamicSharedMemorySize, TG_SMEM);
    cudaFuncSetAttribute(tgemm<EPI_QVAL>,     cudaFuncAttributeMaxDynamicSharedMemorySize, TG_SMEM);
    cudaFuncSetAttribute(tgemm<EPI_PLAIN>,    cudaFuncAttributeMaxDynamicSharedMemorySize, TG_SMEM);
    cudaFuncSetAttribute(tgemm<EPI_COLSCALE>, cudaFuncAttributeMaxDynamicSharedMemorySize, TG_SMEM);
    cudaFuncSetAttribute(tgemm<EPI_T_UPDATE>, cudaFuncAttributeMaxDynamicSharedMemorySize, TG_SMEM);

    const long SCN = (long)C_ * N_;
    const long SDN = (long)D_ * N_;
    const long SNN = (long)N_ * N_;
    const long SND = (long)N_ * D_;

    float* w_conv1 = wts;
    float* w_qv    = wts + SEG_W1;
    float* w_t     = wts + SEG_W1 + SEG_QV;

    dim3 blk(256);
    dim3 gC (N_ / 256, 2, B_);        // M=256
    dim3 gQV(N_ / 256, 3, B_);        // M=320
    dim3 gE (N_ / 256, N_ / 128, B_); // M=N=2048

    prep_kernel<<<(int)((PREP_TOT + 255) / 256), blk>>>(conv1_w, Wqk, Wv, Wt, x,
                                                        convpos, xyz);

    tgemm<EPI_BN_RELU><<<gC, blk, TG_SMEM>>>(
        w_conv1, 0, C_, C_, xrnd, SCN, h0, SCN,
        nullptr, bn1_g, bn1_b, bn1_m, bn1_v,
        nullptr, SCN, pos, hp, nullptr, 0, nullptr, nullptr);

    float* hcur = h0;
    float* hnxt = h1;

    for (int i = 0; i < 4; i++) {
        tgemm<EPI_QVAL><<<gQV, blk, TG_SMEM>>>(
            w_qv + (long)i * 81920, 0, 320, C_, hp, SCN, val, SCN,
            bv + i * C_, nullptr, nullptr, nullptr, nullptr,
            nullptr, SCN, nullptr, nullptr, nullptr, 0, q, qT);

        tgemm<EPI_PLAIN><<<gE, blk, TG_SMEM>>>(
            qT, SND, N_, D_, q, SDN, att, SNN,
            nullptr, nullptr, nullptr, nullptr, nullptr,
            nullptr, SCN, nullptr, nullptr, nullptr, 0, nullptr, nullptr);

        softmax_kernel<<<B_ * N_, blk>>>(att);

        tgemm<EPI_COLSCALE><<<gC, blk, TG_SMEM>>>(
            val, SCN, C_, N_, att, SNN, dbuf, SCN,
            nullptr, nullptr, nullptr, nullptr, nullptr,
            hcur, SCN, nullptr, nullptr, nullptr, 0, nullptr, nullptr);

        tgemm<EPI_T_UPDATE><<<gC, blk, TG_SMEM>>>(
            w_t + (long)i * C_ * C_, 0, C_, C_, dbuf, SCN, hnxt, SCN,
            bt + i * C_, bng + i * C_, bnb + i * C_, bnm + i * C_, bnv + i * C_,
            hcur, SCN, pos, hp,
            out + (long)i * C_ * N_, (long)4 * C_ * N_, nullptr, nullptr);

        float* tmp = hcur; hcur = hnxt; hnxt = tmp;
    }
}

// round 10
// speedup vs baseline: 1.5877x; 1.5877x over previous
#include <cuda_runtime.h>
#include <cuda_fp16.h>
#include <cstdint>

// ---------------------------------------------------------------------------
// PCT position-embedding + 4 offset-attention SA layers. B=8, C=256, D=64,
// N=2048. GEMMs on fp16 mma.sync m16n8k16 (fp32 accum). fp16 has the same
// 11-bit effective mantissa as tf32; the 5-bit exponent is handled by scaling
// softmax probabilities by S=32768 (max safe: probs<=1 -> 32768 < 65504),
// exactly cancelled by the double normalization:
//   x_r = val@(S p) / (S*1e-9 + colsum(S p)).
// Energy matrix stays fp32.
// ---------------------------------------------------------------------------

#define B_   8
#define C_   256
#define D_   64
#define N_   2048
#define PSCALE 32768.0f

__device__ float  g_pos[B_ * C_ * N_];
__device__ float  g_h0 [B_ * C_ * N_];
__device__ float  g_h1 [B_ * C_ * N_];
__device__ __half g_hp [B_ * C_ * N_];
__device__ __half g_xh [B_ * C_ * N_];
__device__ __half g_q  [B_ * D_ * N_];
__device__ __half g_qT [B_ * N_ * D_];
__device__ __half g_val[B_ * C_ * N_];
__device__ __half g_dh [B_ * C_ * N_];
__device__ float  g_att[(long long)B_ * N_ * N_];   // raw energy (fp32!)
__device__ __half g_ath[(long long)B_ * N_ * N_];   // S * softmax probs (fp16)
__device__ __half g_wh [655360];

__device__ __forceinline__ uint32_t smem_u32(const void* p) {
    return (uint32_t)__cvta_generic_to_shared(p);
}
__device__ __forceinline__ uint32_t h2u(__half2 h) {
    return *reinterpret_cast<uint32_t*>(&h);
}

// ---------------------------------------------------------------------------
// warp-tile compute: 64x32 warp tile, fp16 m16n8k16, fp32 accum.
// A smem stride 40 halves (80B), B smem stride 136 halves (272B).
// ---------------------------------------------------------------------------
__device__ __forceinline__ void compute_tile(
    const __half* __restrict__ Asb, const __half* __restrict__ Bsb,
    float acc[4][4][4], int lane, int wm0, int wn0)
{
#pragma unroll
    for (int ks = 0; ks < 2; ks++) {
        uint32_t a[4][4];
#pragma unroll
        for (int mt = 0; mt < 4; mt++) {
            const __half* pa = Asb + (wm0 + mt * 16 + (lane & 15)) * 40
                             + ks * 16 + (lane >> 4) * 8;
            uint32_t ad = smem_u32(pa);
            asm volatile("ldmatrix.sync.aligned.m8n8.x4.shared.b16 {%0,%1,%2,%3}, [%4];"
                : "=r"(a[mt][0]), "=r"(a[mt][1]), "=r"(a[mt][2]), "=r"(a[mt][3])
                : "r"(ad));
        }
        uint32_t b[4][2];
#pragma unroll
        for (int j = 0; j < 2; j++) {
            const __half* pb = Bsb
                + (ks * 16 + (lane & 7) + ((lane >> 3) & 1) * 8) * 136
                + wn0 + j * 16 + (lane >> 4) * 8;
            uint32_t bd = smem_u32(pb);
            uint32_t r0, r1, r2, r3;
            asm volatile("ldmatrix.sync.aligned.m8n8.x4.trans.shared.b16 {%0,%1,%2,%3}, [%4];"
                : "=r"(r0), "=r"(r1), "=r"(r2), "=r"(r3) : "r"(bd));
            b[2 * j][0] = r0; b[2 * j][1] = r1;
            b[2 * j + 1][0] = r2; b[2 * j + 1][1] = r3;
        }
#pragma unroll
        for (int mt = 0; mt < 4; mt++)
#pragma unroll
            for (int nt = 0; nt < 4; nt++) {
                asm volatile(
                    "mma.sync.aligned.m16n8k16.row.col.f32.f16.f16.f32 "
                    "{%0,%1,%2,%3}, {%4,%5,%6,%7}, {%8,%9}, {%0,%1,%2,%3};"
                    : "+f"(acc[mt][nt][0]), "+f"(acc[mt][nt][1]),
                      "+f"(acc[mt][nt][2]), "+f"(acc[mt][nt][3])
                    : "r"(a[mt][0]), "r"(a[mt][1]), "r"(a[mt][2]), "r"(a[mt][3]),
                      "r"(b[nt][0]), "r"(b[nt][1]));
            }
    }
}

// ---------------------------------------------------------------------------
// prep kernel: weights + x to fp16, pos (fp32).
// ---------------------------------------------------------------------------
#define SEG_W1   65536L
#define SEG_QV   327680L
#define SEG_WT   262144L
#define SEG_X    ((long)B_ * C_ * N_)
#define PREP_TOT (SEG_W1 + SEG_QV + SEG_WT + SEG_X + SEG_X)

__global__ void prep_kernel(const float* __restrict__ conv1_w,
                            const float* __restrict__ Wqk,
                            const float* __restrict__ Wv,
                            const float* __restrict__ Wt,
                            const float* __restrict__ x,
                            const float* __restrict__ convpos,
                            const float* __restrict__ xyz)
{
    long i = (long)blockIdx.x * 256 + threadIdx.x;
    if (i >= PREP_TOT) return;
    if (i < SEG_W1) {
        g_wh[i] = __float2half_rn(conv1_w[i]);
    } else if (i < SEG_W1 + SEG_QV) {
        long j = i - SEG_W1;
        int layer = (int)(j / 81920);
        long o = j % 81920;
        float v = (o < 16384) ? Wqk[(long)layer * 16384 + o]
                              : Wv[(long)layer * 65536 + (o - 16384)];
        g_wh[i] = __float2half_rn(v);
    } else if (i < SEG_W1 + SEG_QV + SEG_WT) {
        g_wh[i] = __float2half_rn(Wt[i - SEG_W1 - SEG_QV]);
    } else if (i < SEG_W1 + SEG_QV + SEG_WT + SEG_X) {
        long j = i - SEG_W1 - SEG_QV - SEG_WT;
        g_xh[j] = __float2half_rn(x[j]);
    } else {
        long j = i - SEG_W1 - SEG_QV - SEG_WT - SEG_X;
        int n = (int)(j % N_);
        int c = (int)((j / N_) % C_);
        int b = (int)(j / ((long)C_ * N_));
        const float* pp = xyz + ((long)b * N_ + n) * 3;
        g_pos[j] = convpos[c * 3 + 0] * pp[0] + convpos[c * 3 + 1] * pp[1]
                 + convpos[c * 3 + 2] * pp[2];
    }
}

// ---------------------------------------------------------------------------
// fp16 GEMM, block tile 128x128, 4-stage cp.async ring, 1 barrier/stage.
// ---------------------------------------------------------------------------
enum { EPI_BN_RELU = 0, EPI_QVAL = 1, EPI_PLAIN = 2, EPI_COLSCALE = 3,
       EPI_T_UPDATE = 4 };

#define TG_STAGES   4
#define TG_AS_STR   (128 * 40)               // halves per A stage
#define TG_BS_STR   (32 * 136)               // halves per B stage
#define TG_RING_B   (TG_STAGES * (TG_AS_STR + TG_BS_STR) * 2)   // bytes
#define TG_CS_B     (TG_RING_B)              // csred: 16 x 128 floats
#define TG_CSB_B    (TG_CS_B + 16 * 128 * 4)
#define TG_SMEM     (TG_CSB_B + 128 * 4)

template <int EPI>
__global__ void __launch_bounds__(256, 2)
tgemm(const __half* __restrict__ A, long aStride, int M, int K,
      const __half* __restrict__ Bm, long bStride,
      float* __restrict__ Cf, __half* __restrict__ Ch, long cStride,
      const float* __restrict__ bias,
      const float* __restrict__ bng, const float* __restrict__ bnb,
      const float* __restrict__ bnm, const float* __restrict__ bnv,
      const float* __restrict__ hres, long hresStride,
      const float* __restrict__ posB,
      __half* __restrict__ hpOut,
      float* __restrict__ out2, long out2Stride,
      __half* __restrict__ qB, __half* __restrict__ qTB)
{
    extern __shared__ char smd[];
    __half* AsBase = reinterpret_cast<__half*>(smd);
    __half* BsBase = AsBase + TG_STAGES * TG_AS_STR;
    float (*csred)[128] = reinterpret_cast<float(*)[128]>(smd + TG_CS_B);
    float* csb = reinterpret_cast<float*>(smd + TG_CSB_B);

    const int bz = blockIdx.z;
    const __half* Ab = A + (long)bz * aStride;
    const __half* Bb = Bm + (long)bz * bStride;

    const int m0 = blockIdx.y * 128;
    const int n0 = blockIdx.x * 128;
    const int t  = threadIdx.x;
    const int lane = t & 31;
    const int w    = t >> 5;
    const int g  = lane >> 2, tg = lane & 3;
    const int wm0 = (w >> 2) * 64, wn0 = (w & 3) * 32;

    float acc[4][4][4];
#pragma unroll
    for (int i = 0; i < 4; i++)
#pragma unroll
        for (int j = 0; j < 4; j++)
#pragma unroll
            for (int k = 0; k < 4; k++) acc[i][j][k] = 0.f;

    float csum[8];
    if (EPI == EPI_COLSCALE) {
#pragma unroll
        for (int j = 0; j < 8; j++) csum[j] = 0.f;
    }

    // loaders: A tile 128 rows x 32 halves; B tile 32 rows x 128 halves
    const int aRow = t >> 2, aCg = (t & 3) * 8;
    const int bRow = t >> 4, bCg = (t & 15) * 8;
    const int nStages = K >> 5;                      // kTile = 32 halves

    // prologue: always commit TG_STAGES-1 groups (empty if past nStages)
#pragma unroll
    for (int s = 0; s < TG_STAGES - 1; s++) {
        if (s < nStages) {
            const int k0 = s * 32;
            __half* As = AsBase + s * TG_AS_STR;
            __half* Bs = BsBase + s * TG_BS_STR;
#pragma unroll
            for (int h = 0; h < 2; h++) {
                int row = aRow + h * 64;
                if (m0 + row < M) {
                    uint32_t dst = smem_u32(As + row * 40 + aCg);
                    const __half* src = Ab + (long)(m0 + row) * K + k0 + aCg;
                    asm volatile("cp.async.cg.shared.global [%0], [%1], 16;" :: "r"(dst), "l"(src));
                }
            }
#pragma unroll
            for (int h = 0; h < 2; h++) {
                int row = bRow + h * 16;
                uint32_t dst = smem_u32(Bs + row * 136 + bCg);
                const __half* src = Bb + (long)(k0 + row) * N_ + n0 + bCg;
                asm volatile("cp.async.cg.shared.global [%0], [%1], 16;" :: "r"(dst), "l"(src));
            }
        }
        asm volatile("cp.async.commit_group;");
    }

    for (int s = 0; s < nStages; s++) {
        const int buf = s & (TG_STAGES - 1);
        asm volatile("cp.async.wait_group %0;" :: "n"(TG_STAGES - 2));
        __syncthreads();

        const int sn = s + TG_STAGES - 1;
        if (sn < nStages) {
            const int k0 = sn * 32, nb = sn & (TG_STAGES - 1);
            __half* As = AsBase + nb * TG_AS_STR;
            __half* Bs = BsBase + nb * TG_BS_STR;
#pragma unroll
            for (int h = 0; h < 2; h++) {
                int row = aRow + h * 64;
                if (m0 + row < M) {
                    uint32_t dst = smem_u32(As + row * 40 + aCg);
                    const __half* src = Ab + (long)(m0 + row) * K + k0 + aCg;
                    asm volatile("cp.async.cg.shared.global [%0], [%1], 16;" :: "r"(dst), "l"(src));
                }
            }
#pragma unroll
            for (int h = 0; h < 2; h++) {
                int row = bRow + h * 16;
                uint32_t dst = smem_u32(Bs + row * 136 + bCg);
                const __half* src = Bb + (long)(k0 + row) * N_ + n0 + bCg;
                asm volatile("cp.async.cg.shared.global [%0], [%1], 16;" :: "r"(dst), "l"(src));
            }
        }
        asm volatile("cp.async.commit_group;");

        const __half* AsC = AsBase + buf * TG_AS_STR;
        const __half* BsC = BsBase + buf * TG_BS_STR;

        if (EPI == EPI_COLSCALE) {
#pragma unroll
            for (int h = 0; h < 2; h++) {
                const __half2* pv = reinterpret_cast<const __half2*>(
                    BsC + (bRow + h * 16) * 136 + bCg);
#pragma unroll
                for (int j = 0; j < 4; j++) {
                    float2 f = __half22float2(pv[j]);
                    csum[2 * j] += f.x; csum[2 * j + 1] += f.y;
                }
            }
        }
        compute_tile(AsC, BsC, acc, lane, wm0, wn0);
    }

    if (EPI == EPI_COLSCALE) {
        __syncthreads();
#pragma unroll
        for (int j = 0; j < 8; j++) csred[bRow][bCg + j] = csum[j];
        __syncthreads();
        if (t < 128) {
            float ssum = 0.f;
#pragma unroll
            for (int r = 0; r < 16; r++) ssum += csred[r][t];
            // probs were scaled by PSCALE -> denominator 1e-9 scales too
            csb[t] = 1.f / (PSCALE * 1e-9f + ssum);
        }
        __syncthreads();
    }

    const long cOff = (long)bz * cStride;
#pragma unroll
    for (int mt = 0; mt < 4; mt++) {
#pragma unroll
        for (int half_ = 0; half_ < 2; half_++) {
            const int r = m0 + wm0 + mt * 16 + g + half_ * 8;
            if (r >= M) continue;

            float sc = 1.f, sh = 0.f, bsv = 0.f;
            if (EPI == EPI_BN_RELU || EPI == EPI_T_UPDATE) {
                float inv = rsqrtf(bnv[r] + 1e-5f);
                sc = bng[r] * inv; sh = bnb[r] - bnm[r] * sc;
            }
            if (EPI == EPI_T_UPDATE) bsv = bias[r];

#pragma unroll
            for (int nt = 0; nt < 4; nt++) {
                const int cb = n0 + wn0 + nt * 8 + 2 * tg;
                float v0 = acc[mt][nt][half_ * 2 + 0];
                float v1 = acc[mt][nt][half_ * 2 + 1];
                long rowoff = (long)r * N_ + cb;

                if (EPI == EPI_BN_RELU) {
                    v0 = fmaxf(fmaf(v0, sc, sh), 0.f);
                    v1 = fmaxf(fmaf(v1, sc, sh), 0.f);
                    *reinterpret_cast<float2*>(Cf + cOff + rowoff) = make_float2(v0, v1);
                    const float* pb = posB + (long)bz * hresStride;
                    float2 p2 = *reinterpret_cast<const float2*>(pb + rowoff);
                    __half2* hbp = reinterpret_cast<__half2*>(
                        hpOut + (long)bz * hresStride + rowoff);
                    *hbp = __floats2half2_rn(v0 + p2.x, v1 + p2.y);
                } else if (EPI == EPI_QVAL) {
                    if (r < 64) {
                        __half q0 = __float2half_rn(v0), q1 = __float2half_rn(v1);
                        __half* qb = qB + (long)bz * ((long)D_ * N_);
                        *reinterpret_cast<__half2*>(qb + (long)r * N_ + cb) =
                            __halves2half2(q0, q1);
                        __half* qt = qTB + (long)bz * ((long)N_ * D_);
                        qt[(long)cb * D_ + r]       = q0;
                        qt[(long)(cb + 1) * D_ + r] = q1;
                    } else {
                        float bv2 = bias[r - 64];
                        long vo = (long)(r - 64) * N_ + cb;
                        *reinterpret_cast<__half2*>(Ch + cOff + vo) =
                            __floats2half2_rn(v0 + bv2, v1 + bv2);
                    }
                } else if (EPI == EPI_PLAIN) {
                    *reinterpret_cast<float2*>(Cf + cOff + rowoff) = make_float2(v0, v1);
                } else if (EPI == EPI_COLSCALE) {
                    float i0 = csb[cb - n0], i1 = csb[cb - n0 + 1];
                    const float* hb = hres + (long)bz * hresStride;
                    float2 h2 = *reinterpret_cast<const float2*>(hb + rowoff);
                    *reinterpret_cast<__half2*>(Ch + cOff + rowoff) =
                        __floats2half2_rn(h2.x - v0 * i0, h2.y - v1 * i1);
                } else { // EPI_T_UPDATE
                    v0 = fmaxf(fmaf(v0 + bsv, sc, sh), 0.f);
                    v1 = fmaxf(fmaf(v1 + bsv, sc, sh), 0.f);
                    const float* hb = hres + (long)bz * hresStride;
                    float2 h2 = *reinterpret_cast<const float2*>(hb + rowoff);
                    float o0 = v0 + h2.x, o1 = v1 + h2.y;
                    *reinterpret_cast<float2*>(Cf + cOff + rowoff) = make_float2(o0, o1);
                    float* ob = out2 + (long)bz * out2Stride;
                    *reinterpret_cast<float2*>(ob + rowoff) = make_float2(o0, o1);
                    const float* pb = posB + (long)bz * hresStride;
                    float2 p2 = *reinterpret_cast<const float2*>(pb + rowoff);
                    __half2* hb2 = reinterpret_cast<__half2*>(
                        hpOut + (long)bz * hresStride + rowoff);
                    *hb2 = __floats2half2_rn(o0 + p2.x, o1 + p2.y);
                }
            }
        }
    }
}

// ---------------------------------------------------------------------------
// Row softmax: reads fp32 energy, writes PSCALE * probability in fp16.
// ---------------------------------------------------------------------------
__global__ void __launch_bounds__(256)
softmax_kernel(const float* __restrict__ E, __half* __restrict__ P)
{
    long row = blockIdx.x;
    const float4* r = reinterpret_cast<const float4*>(E + row * (long)N_);
    const int t = threadIdx.x;

    float4 va = r[t];
    float4 vb = r[t + 256];
    float mx = fmaxf(fmaxf(fmaxf(va.x, va.y), fmaxf(va.z, va.w)),
                     fmaxf(fmaxf(vb.x, vb.y), fmaxf(vb.z, vb.w)));

    __shared__ float red[8];
#pragma unroll
    for (int o = 16; o > 0; o >>= 1) mx = fmaxf(mx, __shfl_xor_sync(0xffffffffu, mx, o));
    if ((t & 31) == 0) red[t >> 5] = mx;
    __syncthreads();
    float bm = red[0];
#pragma unroll
    for (int w = 1; w < 8; w++) bm = fmaxf(bm, red[w]);
    __syncthreads();

    va.x = __expf(va.x - bm); va.y = __expf(va.y - bm);
    va.z = __expf(va.z - bm); va.w = __expf(va.w - bm);
    vb.x = __expf(vb.x - bm); vb.y = __expf(vb.y - bm);
    vb.z = __expf(vb.z - bm); vb.w = __expf(vb.w - bm);
    float sum = va.x + va.y + va.z + va.w + vb.x + vb.y + vb.z + vb.w;
#pragma unroll
    for (int o = 16; o > 0; o >>= 1) sum += __shfl_xor_sync(0xffffffffu, sum, o);
    if ((t & 31) == 0) red[t >> 5] = sum;
    __syncthreads();
    float tot = 0.f;
#pragma unroll
    for (int w = 0; w < 8; w++) tot += red[w];
    float inv = PSCALE / tot;   // scaled probabilities keep fp16 exponent range

    uint2 o0, o1;
    o0.x = h2u(__floats2half2_rn(va.x * inv, va.y * inv));
    o0.y = h2u(__floats2half2_rn(va.z * inv, va.w * inv));
    o1.x = h2u(__floats2half2_rn(vb.x * inv, vb.y * inv));
    o1.y = h2u(__floats2half2_rn(vb.z * inv, vb.w * inv));
    uint2* po = reinterpret_cast<uint2*>(P + row * (long)N_);
    po[t]       = o0;
    po[t + 256] = o1;
}

// ---------------------------------------------------------------------------
extern "C" void kernel_launch(void* const* d_in, const int* in_sizes, int n_in,
                              void* d_out, int out_size)
{
    (void)in_sizes; (void)n_in; (void)out_size;

    const float* x       = (const float*)d_in[0];
    const float* xyz     = (const float*)d_in[1];
    const float* conv1_w = (const float*)d_in[2];
    const float* convpos = (const float*)d_in[3];
    const float* bn1_g   = (const float*)d_in[4];
    const float* bn1_b   = (const float*)d_in[5];
    const float* bn1_m   = (const float*)d_in[6];
    const float* bn1_v   = (const float*)d_in[7];
    const float* Wqk     = (const float*)d_in[8];
    const float* Wv      = (const float*)d_in[9];
    const float* bv      = (const float*)d_in[10];
    const float* Wt      = (const float*)d_in[11];
    const float* bt      = (const float*)d_in[12];
    const float* bng     = (const float*)d_in[13];
    const float* bnb     = (const float*)d_in[14];
    const float* bnm     = (const float*)d_in[15];
    const float* bnv     = (const float*)d_in[16];
    float* out = (float*)d_out;

    float  *pos, *h0, *h1, *att;
    __half *hp, *xh, *q, *qT, *val, *dh, *ath, *wh;
    cudaGetSymbolAddress((void**)&pos, g_pos);
    cudaGetSymbolAddress((void**)&h0,  g_h0);
    cudaGetSymbolAddress((void**)&h1,  g_h1);
    cudaGetSymbolAddress((void**)&att, g_att);
    cudaGetSymbolAddress((void**)&hp,  g_hp);
    cudaGetSymbolAddress((void**)&xh,  g_xh);
    cudaGetSymbolAddress((void**)&q,   g_q);
    cudaGetSymbolAddress((void**)&qT,  g_qT);
    cudaGetSymbolAddress((void**)&val, g_val);
    cudaGetSymbolAddress((void**)&dh,  g_dh);
    cudaGetSymbolAddress((void**)&ath, g_ath);
    cudaGetSymbolAddress((void**)&wh,  g_wh);

    cudaFuncSetAttribute(tgemm<EPI_BN_RELU>,  cudaFuncAttributeMaxDynamicSharedMemorySize, TG_SMEM);
    cudaFuncSetAttribute(tgemm<EPI_QVAL>,     cudaFuncAttributeMaxDynamicSharedMemorySize, TG_SMEM);
    cudaFuncSetAttribute(tgemm<EPI_PLAIN>,    cudaFuncAttributeMaxDynamicSharedMemorySize, TG_SMEM);
    cudaFuncSetAttribute(tgemm<EPI_COLSCALE>, cudaFuncAttributeMaxDynamicSharedMemorySize, TG_SMEM);
    cudaFuncSetAttribute(tgemm<EPI_T_UPDATE>, cudaFuncAttributeMaxDynamicSharedMemorySize, TG_SMEM);

    const long SCN = (long)C_ * N_;
    const long SDN = (long)D_ * N_;
    const long SNN = (long)N_ * N_;
    const long SND = (long)N_ * D_;

    __half* w_conv1 = wh;
    __half* w_qv    = wh + SEG_W1;
    __half* w_t     = wh + SEG_W1 + SEG_QV;

    dim3 blk(256);
    dim3 gC (N_ / 128, 2, B_);        // M=256
    dim3 gQV(N_ / 128, 3, B_);        // M=320
    dim3 gE (N_ / 128, N_ / 128, B_); // M=N=2048

    prep_kernel<<<(int)((PREP_TOT + 255) / 256), blk>>>(conv1_w, Wqk, Wv, Wt, x,
                                                        convpos, xyz);

    // h0 = relu(bn1(conv1 @ x)); hp = half(h0 + pos)
    tgemm<EPI_BN_RELU><<<gC, blk, TG_SMEM>>>(
        w_conv1, 0, C_, C_, xh, SCN, h0, nullptr, SCN,
        nullptr, bn1_g, bn1_b, bn1_m, bn1_v,
        nullptr, SCN, pos, hp, nullptr, 0, nullptr, nullptr);

    float* hcur = h0;
    float* hnxt = h1;

    for (int i = 0; i < 4; i++) {
        // [q;val] = [Wqk;Wv] @ hp
        tgemm<EPI_QVAL><<<gQV, blk, TG_SMEM>>>(
            w_qv + (long)i * 81920, 0, 320, C_, hp, SCN, nullptr, val, SCN,
            bv + i * C_, nullptr, nullptr, nullptr, nullptr,
            nullptr, SCN, nullptr, nullptr, nullptr, 0, q, qT);

        // energy = qT @ q   (fp32 output)
        tgemm<EPI_PLAIN><<<gE, blk, TG_SMEM>>>(
            qT, SND, N_, D_, q, SDN, att, nullptr, SNN,
            nullptr, nullptr, nullptr, nullptr, nullptr,
            nullptr, SCN, nullptr, nullptr, nullptr, 0, nullptr, nullptr);

        // softmax fp32 -> PSCALE * prob in fp16
        softmax_kernel<<<B_ * N_, blk>>>(att, ath);

        // dh = half(h - (val @ pS) / (PSCALE*1e-9 + colsum_S))
        tgemm<EPI_COLSCALE><<<gC, blk, TG_SMEM>>>(
            val, SCN, C_, N_, ath, SNN, nullptr, dh, SCN,
            nullptr, nullptr, nullptr, nullptr, nullptr,
            hcur, SCN, nullptr, nullptr, nullptr, 0, nullptr, nullptr);

        // h_new = h + relu(bn(Wt @ dh + bt)); out slice; hp = half(h_new + pos)
        tgemm<EPI_T_UPDATE><<<gC, blk, TG_SMEM>>>(
            w_t + (long)i * C_ * C_, 0, C_, C_, dh, SCN, hnxt, nullptr, SCN,
            bt + i * C_, bng + i * C_, bnb + i * C_, bnm + i * C_, bnv + i * C_,
            hcur, SCN, pos, hp,
            out + (long)i * C_ * N_, (long)4 * C_ * N_, nullptr, nullptr);

        float* tmp = hcur; hcur = hnxt; hnxt = tmp;
    }
}

// round 11
// speedup vs baseline: 1.6281x; 1.0255x over previous
#include <cuda_runtime.h>
#include <cuda_fp16.h>
#include <cstdint>

// ---------------------------------------------------------------------------
// PCT position-embedding + 4 offset-attention SA layers. B=8, C=256, D=64,
// N=2048. fp16 mma.sync m16n8k16 (fp32 accum), PSCALE'd softmax probs.
// Softmax pass eliminated: energy GEMM emits p~ = PSCALE*exp(e - tilemax)
// in fp16 + per-tile row stats; a tiny rowstats kernel computes
// s[n,t] = exp(tmax-rmax)/rsum; the xr GEMM applies s inside the B fragments
// (exact algebra: p = p~ * s).
// ---------------------------------------------------------------------------

#define B_   8
#define C_   256
#define D_   64
#define N_   2048
#define PSCALE 32768.0f
#define NT_  16                       // N_/128 column tiles

__device__ float  g_pos[B_ * C_ * N_];
__device__ float  g_h0 [B_ * C_ * N_];
__device__ float  g_h1 [B_ * C_ * N_];
__device__ __half g_hp [B_ * C_ * N_];
__device__ __half g_xh [B_ * C_ * N_];
__device__ __half g_q  [B_ * D_ * N_];
__device__ __half g_qT [B_ * N_ * D_];
__device__ __half g_val[B_ * C_ * N_];
__device__ __half g_dh [B_ * C_ * N_];
__device__ __half g_ath[(long long)B_ * N_ * N_];   // p~ (fp16)
__device__ float2 g_tstat[B_ * NT_ * N_];           // {tilemax, tilesum}
__device__ float  g_s   [B_ * NT_ * N_];            // s[n,t]
__device__ __half g_wh [655360];

__device__ __forceinline__ uint32_t smem_u32(const void* p) {
    return (uint32_t)__cvta_generic_to_shared(p);
}
__device__ __forceinline__ uint32_t h2u(__half2 h) {
    return *reinterpret_cast<uint32_t*>(&h);
}

// ---------------------------------------------------------------------------
// warp-tile compute: 64x32 warp tile, fp16 m16n8k16, fp32 accum.
// SCALE variant multiplies B fragments by per-k fp32 scales from sst[32]
// and accumulates column sums of the scaled B into csumF[4].
// ---------------------------------------------------------------------------
template <bool SCALE>
__device__ __forceinline__ void compute_tile(
    const __half* __restrict__ Asb, const __half* __restrict__ Bsb,
    float acc[4][4][4], int lane, int wm0, int wn0,
    const float* __restrict__ sst, float* __restrict__ csumF)
{
    const int tg = lane & 3;
#pragma unroll
    for (int ks = 0; ks < 2; ks++) {
        uint32_t a[4][4];
#pragma unroll
        for (int mt = 0; mt < 4; mt++) {
            const __half* pa = Asb + (wm0 + mt * 16 + (lane & 15)) * 40
                             + ks * 16 + (lane >> 4) * 8;
            uint32_t ad = smem_u32(pa);
            asm volatile("ldmatrix.sync.aligned.m8n8.x4.shared.b16 {%0,%1,%2,%3}, [%4];"
                : "=r"(a[mt][0]), "=r"(a[mt][1]), "=r"(a[mt][2]), "=r"(a[mt][3])
                : "r"(ad));
        }
        uint32_t b[4][2];
#pragma unroll
        for (int j = 0; j < 2; j++) {
            const __half* pb = Bsb
                + (ks * 16 + (lane & 7) + ((lane >> 3) & 1) * 8) * 136
                + wn0 + j * 16 + (lane >> 4) * 8;
            uint32_t bd = smem_u32(pb);
            uint32_t r0, r1, r2, r3;
            asm volatile("ldmatrix.sync.aligned.m8n8.x4.trans.shared.b16 {%0,%1,%2,%3}, [%4];"
                : "=r"(r0), "=r"(r1), "=r"(r2), "=r"(r3) : "r"(bd));
            b[2 * j][0] = r0; b[2 * j][1] = r1;
            b[2 * j + 1][0] = r2; b[2 * j + 1][1] = r3;
        }
        if (SCALE) {
            // b[nt][0] holds k = ks*16 + 2tg,+1 ; b[nt][1] holds +8,+9
            float2 sA = *reinterpret_cast<const float2*>(&sst[ks * 16 + 2 * tg]);
            float2 sB = *reinterpret_cast<const float2*>(&sst[ks * 16 + 8 + 2 * tg]);
#pragma unroll
            for (int nt = 0; nt < 4; nt++) {
                __half2 h0v = *reinterpret_cast<__half2*>(&b[nt][0]);
                float2 f0 = __half22float2(h0v);
                f0.x *= sA.x; f0.y *= sA.y;
                b[nt][0] = h2u(__floats2half2_rn(f0.x, f0.y));
                __half2 h1v = *reinterpret_cast<__half2*>(&b[nt][1]);
                float2 f1 = __half22float2(h1v);
                f1.x *= sB.x; f1.y *= sB.y;
                b[nt][1] = h2u(__floats2half2_rn(f1.x, f1.y));
                csumF[nt] += (f0.x + f0.y) + (f1.x + f1.y);
            }
        }
#pragma unroll
        for (int mt = 0; mt < 4; mt++)
#pragma unroll
            for (int nt = 0; nt < 4; nt++) {
                asm volatile(
                    "mma.sync.aligned.m16n8k16.row.col.f32.f16.f16.f32 "
                    "{%0,%1,%2,%3}, {%4,%5,%6,%7}, {%8,%9}, {%0,%1,%2,%3};"
                    : "+f"(acc[mt][nt][0]), "+f"(acc[mt][nt][1]),
                      "+f"(acc[mt][nt][2]), "+f"(acc[mt][nt][3])
                    : "r"(a[mt][0]), "r"(a[mt][1]), "r"(a[mt][2]), "r"(a[mt][3]),
                      "r"(b[nt][0]), "r"(b[nt][1]));
            }
    }
}

// ---------------------------------------------------------------------------
// prep kernel: weights + x to fp16, pos (fp32).
// ---------------------------------------------------------------------------
#define SEG_W1   65536L
#define SEG_QV   327680L
#define SEG_WT   262144L
#define SEG_X    ((long)B_ * C_ * N_)
#define PREP_TOT (SEG_W1 + SEG_QV + SEG_WT + SEG_X + SEG_X)

__global__ void prep_kernel(const float* __restrict__ conv1_w,
                            const float* __restrict__ Wqk,
                            const float* __restrict__ Wv,
                            const float* __restrict__ Wt,
                            const float* __restrict__ x,
                            const float* __restrict__ convpos,
                            const float* __restrict__ xyz)
{
    long i = (long)blockIdx.x * 256 + threadIdx.x;
    if (i >= PREP_TOT) return;
    if (i < SEG_W1) {
        g_wh[i] = __float2half_rn(conv1_w[i]);
    } else if (i < SEG_W1 + SEG_QV) {
        long j = i - SEG_W1;
        int layer = (int)(j / 81920);
        long o = j % 81920;
        float v = (o < 16384) ? Wqk[(long)layer * 16384 + o]
                              : Wv[(long)layer * 65536 + (o - 16384)];
        g_wh[i] = __float2half_rn(v);
    } else if (i < SEG_W1 + SEG_QV + SEG_WT) {
        g_wh[i] = __float2half_rn(Wt[i - SEG_W1 - SEG_QV]);
    } else if (i < SEG_W1 + SEG_QV + SEG_WT + SEG_X) {
        long j = i - SEG_W1 - SEG_QV - SEG_WT;
        g_xh[j] = __float2half_rn(x[j]);
    } else {
        long j = i - SEG_W1 - SEG_QV - SEG_WT - SEG_X;
        int n = (int)(j % N_);
        int c = (int)((j / N_) % C_);
        int b = (int)(j / ((long)C_ * N_));
        const float* pp = xyz + ((long)b * N_ + n) * 3;
        g_pos[j] = convpos[c * 3 + 0] * pp[0] + convpos[c * 3 + 1] * pp[1]
                 + convpos[c * 3 + 2] * pp[2];
    }
}

// ---------------------------------------------------------------------------
// fp16 GEMM, block tile 128x128, 4-stage cp.async ring, 1 barrier/stage.
// ---------------------------------------------------------------------------
enum { EPI_BN_RELU = 0, EPI_QVAL = 1, EPI_EXPTILE = 2, EPI_COLSCALE = 3,
       EPI_T_UPDATE = 4 };

#define TG_STAGES   4
#define TG_AS_STR   (128 * 40)               // halves per A stage
#define TG_BS_STR   (32 * 136)               // halves per B stage
#define TG_RING_B   (TG_STAGES * (TG_AS_STR + TG_BS_STR) * 2)
#define TG_CS_B     (TG_RING_B)              // red4: 128 x 4 floats (2KB, also csred)
#define TG_CSB_B    (TG_CS_B + 16 * 128 * 4)
#define TG_SR_B     (TG_CSB_B + 128 * 4)     // s ring: 4 stages x 32 floats
#define TG_SMEM     (TG_SR_B + TG_STAGES * 32 * 4)

template <int EPI>
__global__ void __launch_bounds__(256, 2)
tgemm(const __half* __restrict__ A, long aStride, int M, int K,
      const __half* __restrict__ Bm, long bStride,
      float* __restrict__ Cf, __half* __restrict__ Ch, long cStride,
      const float* __restrict__ bias,
      const float* __restrict__ bng, const float* __restrict__ bnb,
      const float* __restrict__ bnm, const float* __restrict__ bnv,
      const float* __restrict__ hres, long hresStride,
      const float* __restrict__ posB,
      __half* __restrict__ hpOut,
      float* __restrict__ out2, long out2Stride,
      __half* __restrict__ qB, __half* __restrict__ qTB,
      float2* __restrict__ tstatOut, const float* __restrict__ sArr)
{
    extern __shared__ char smd[];
    __half* AsBase = reinterpret_cast<__half*>(smd);
    __half* BsBase = AsBase + TG_STAGES * TG_AS_STR;
    float (*red4)[4] = reinterpret_cast<float(*)[4]>(smd + TG_CS_B);
    float* csb   = reinterpret_cast<float*>(smd + TG_CSB_B);
    float* sring = reinterpret_cast<float*>(smd + TG_SR_B);

    const int bz = blockIdx.z;
    const __half* Ab = A + (long)bz * aStride;
    const __half* Bb = Bm + (long)bz * bStride;
    const float* sBase = (EPI == EPI_COLSCALE)
        ? (sArr + (((long)bz * NT_ + blockIdx.x) << 11)) : nullptr;

    const int m0 = blockIdx.y * 128;
    const int n0 = blockIdx.x * 128;
    const int t  = threadIdx.x;
    const int lane = t & 31;
    const int w    = t >> 5;
    const int g  = lane >> 2, tg = lane & 3;
    const int wm0 = (w >> 2) * 64, wn0 = (w & 3) * 32;

    float acc[4][4][4];
#pragma unroll
    for (int i = 0; i < 4; i++)
#pragma unroll
        for (int j = 0; j < 4; j++)
#pragma unroll
            for (int k = 0; k < 4; k++) acc[i][j][k] = 0.f;

    float csumF[4] = {0.f, 0.f, 0.f, 0.f};

    const int aRow = t >> 2, aCg = (t & 3) * 8;
    const int bRow = t >> 4, bCg = (t & 15) * 8;
    const int nStages = K >> 5;

    // prologue
#pragma unroll
    for (int s = 0; s < TG_STAGES - 1; s++) {
        if (s < nStages) {
            const int k0 = s * 32;
            __half* As = AsBase + s * TG_AS_STR;
            __half* Bs = BsBase + s * TG_BS_STR;
#pragma unroll
            for (int h = 0; h < 2; h++) {
                int row = aRow + h * 64;
                if (m0 + row < M) {
                    uint32_t dst = smem_u32(As + row * 40 + aCg);
                    const __half* src = Ab + (long)(m0 + row) * K + k0 + aCg;
                    asm volatile("cp.async.cg.shared.global [%0], [%1], 16;" :: "r"(dst), "l"(src));
                }
            }
#pragma unroll
            for (int h = 0; h < 2; h++) {
                int row = bRow + h * 16;
                uint32_t dst = smem_u32(Bs + row * 136 + bCg);
                const __half* src = Bb + (long)(k0 + row) * N_ + n0 + bCg;
                asm volatile("cp.async.cg.shared.global [%0], [%1], 16;" :: "r"(dst), "l"(src));
            }
            if (EPI == EPI_COLSCALE && t < 8) {
                uint32_t dst = smem_u32(sring + s * 32 + t * 4);
                const float* src = sBase + k0 + t * 4;
                asm volatile("cp.async.cg.shared.global [%0], [%1], 16;" :: "r"(dst), "l"(src));
            }
        }
        asm volatile("cp.async.commit_group;");
    }

    for (int s = 0; s < nStages; s++) {
        const int buf = s & (TG_STAGES - 1);
        asm volatile("cp.async.wait_group %0;" :: "n"(TG_STAGES - 2));
        __syncthreads();

        const int sn = s + TG_STAGES - 1;
        if (sn < nStages) {
            const int k0 = sn * 32, nb = sn & (TG_STAGES - 1);
            __half* As = AsBase + nb * TG_AS_STR;
            __half* Bs = BsBase + nb * TG_BS_STR;
#pragma unroll
            for (int h = 0; h < 2; h++) {
                int row = aRow + h * 64;
                if (m0 + row < M) {
                    uint32_t dst = smem_u32(As + row * 40 + aCg);
                    const __half* src = Ab + (long)(m0 + row) * K + k0 + aCg;
                    asm volatile("cp.async.cg.shared.global [%0], [%1], 16;" :: "r"(dst), "l"(src));
                }
            }
#pragma unroll
            for (int h = 0; h < 2; h++) {
                int row = bRow + h * 16;
                uint32_t dst = smem_u32(Bs + row * 136 + bCg);
                const __half* src = Bb + (long)(k0 + row) * N_ + n0 + bCg;
                asm volatile("cp.async.cg.shared.global [%0], [%1], 16;" :: "r"(dst), "l"(src));
            }
            if (EPI == EPI_COLSCALE && t < 8) {
                uint32_t dst = smem_u32(sring + nb * 32 + t * 4);
                const float* src = sBase + k0 + t * 4;
                asm volatile("cp.async.cg.shared.global [%0], [%1], 16;" :: "r"(dst), "l"(src));
            }
        }
        asm volatile("cp.async.commit_group;");

        const __half* AsC = AsBase + buf * TG_AS_STR;
        const __half* BsC = BsBase + buf * TG_BS_STR;
        compute_tile<EPI == EPI_COLSCALE>(AsC, BsC, acc, lane, wm0, wn0,
                                          sring + buf * 32, csumF);
    }

    const long cOff = (long)bz * cStride;

    // ------- EXPTILE epilogue: per-tile softmax numerator + stats -------
    if (EPI == EPI_EXPTILE) {
        __syncthreads();
        // 1) per-thread row max over this warp's 32 cols, reduce over quad
        float tmaxv[4][2];
#pragma unroll
        for (int mt = 0; mt < 4; mt++)
#pragma unroll
            for (int hf = 0; hf < 2; hf++) {
                float mval = -3.4e38f;
#pragma unroll
                for (int nt = 0; nt < 4; nt++) {
                    mval = fmaxf(mval, acc[mt][nt][hf * 2 + 0]);
                    mval = fmaxf(mval, acc[mt][nt][hf * 2 + 1]);
                }
                mval = fmaxf(mval, __shfl_xor_sync(0xffffffffu, mval, 1));
                mval = fmaxf(mval, __shfl_xor_sync(0xffffffffu, mval, 2));
                tmaxv[mt][hf] = mval;
            }
        if (tg == 0) {
#pragma unroll
            for (int mt = 0; mt < 4; mt++)
#pragma unroll
                for (int hf = 0; hf < 2; hf++)
                    red4[wm0 + mt * 16 + g + hf * 8][w & 3] = tmaxv[mt][hf];
        }
        __syncthreads();
#pragma unroll
        for (int mt = 0; mt < 4; mt++)
#pragma unroll
            for (int hf = 0; hf < 2; hf++) {
                const float* rr = red4[wm0 + mt * 16 + g + hf * 8];
                tmaxv[mt][hf] = fmaxf(fmaxf(rr[0], rr[1]), fmaxf(rr[2], rr[3]));
            }
        __syncthreads();
        // 2) exp + row partial sums
        float psum[4][2];
#pragma unroll
        for (int mt = 0; mt < 4; mt++)
#pragma unroll
            for (int hf = 0; hf < 2; hf++) {
                float s2 = 0.f;
#pragma unroll
                for (int nt = 0; nt < 4; nt++) {
                    float e0 = __expf(acc[mt][nt][hf * 2 + 0] - tmaxv[mt][hf]);
                    float e1 = __expf(acc[mt][nt][hf * 2 + 1] - tmaxv[mt][hf]);
                    acc[mt][nt][hf * 2 + 0] = e0;
                    acc[mt][nt][hf * 2 + 1] = e1;
                    s2 += e0 + e1;
                }
                s2 += __shfl_xor_sync(0xffffffffu, s2, 1);
                s2 += __shfl_xor_sync(0xffffffffu, s2, 2);
                psum[mt][hf] = s2;
            }
        if (tg == 0) {
#pragma unroll
            for (int mt = 0; mt < 4; mt++)
#pragma unroll
                for (int hf = 0; hf < 2; hf++)
                    red4[wm0 + mt * 16 + g + hf * 8][w & 3] = psum[mt][hf];
        }
        __syncthreads();
        // 3) write p~ and stats
#pragma unroll
        for (int mt = 0; mt < 4; mt++)
#pragma unroll
            for (int hf = 0; hf < 2; hf++) {
                const int rl = wm0 + mt * 16 + g + hf * 8;
                const int r = m0 + rl;
#pragma unroll
                for (int nt = 0; nt < 4; nt++) {
                    const int cb = n0 + wn0 + nt * 8 + 2 * tg;
                    *reinterpret_cast<__half2*>(Ch + cOff + (long)r * N_ + cb) =
                        __floats2half2_rn(PSCALE * acc[mt][nt][hf * 2 + 0],
                                          PSCALE * acc[mt][nt][hf * 2 + 1]);
                }
                if ((w & 3) == 0 && tg == 0) {
                    const float* rr = red4[rl];
                    tstatOut[(((long)bz * NT_ + blockIdx.x) << 11) + r] =
                        make_float2(tmaxv[mt][hf], rr[0] + rr[1] + rr[2] + rr[3]);
                }
            }
        return;
    }

    if (EPI == EPI_COLSCALE) {
        __syncthreads();
#pragma unroll
        for (int nt = 0; nt < 4; nt++) {
            csumF[nt] += __shfl_xor_sync(0xffffffffu, csumF[nt], 1);
            csumF[nt] += __shfl_xor_sync(0xffffffffu, csumF[nt], 2);
        }
        if (w < 4 && tg == 0) {
#pragma unroll
            for (int nt = 0; nt < 4; nt++)
                csb[wn0 + nt * 8 + g] = 1.f / (PSCALE * 1e-9f + csumF[nt]);
        }
        __syncthreads();
    }

#pragma unroll
    for (int mt = 0; mt < 4; mt++) {
#pragma unroll
        for (int half_ = 0; half_ < 2; half_++) {
            const int r = m0 + wm0 + mt * 16 + g + half_ * 8;
            if (r >= M) continue;

            float sc = 1.f, sh = 0.f, bsv = 0.f;
            if (EPI == EPI_BN_RELU || EPI == EPI_T_UPDATE) {
                float inv = rsqrtf(bnv[r] + 1e-5f);
                sc = bng[r] * inv; sh = bnb[r] - bnm[r] * sc;
            }
            if (EPI == EPI_T_UPDATE) bsv = bias[r];

#pragma unroll
            for (int nt = 0; nt < 4; nt++) {
                const int cb = n0 + wn0 + nt * 8 + 2 * tg;
                float v0 = acc[mt][nt][half_ * 2 + 0];
                float v1 = acc[mt][nt][half_ * 2 + 1];
                long rowoff = (long)r * N_ + cb;

                if (EPI == EPI_BN_RELU) {
                    v0 = fmaxf(fmaf(v0, sc, sh), 0.f);
                    v1 = fmaxf(fmaf(v1, sc, sh), 0.f);
                    *reinterpret_cast<float2*>(Cf + cOff + rowoff) = make_float2(v0, v1);
                    const float* pb = posB + (long)bz * hresStride;
                    float2 p2 = *reinterpret_cast<const float2*>(pb + rowoff);
                    __half2* hbp = reinterpret_cast<__half2*>(
                        hpOut + (long)bz * hresStride + rowoff);
                    *hbp = __floats2half2_rn(v0 + p2.x, v1 + p2.y);
                } else if (EPI == EPI_QVAL) {
                    if (r < 64) {
                        __half q0 = __float2half_rn(v0), q1 = __float2half_rn(v1);
                        __half* qb = qB + (long)bz * ((long)D_ * N_);
                        *reinterpret_cast<__half2*>(qb + (long)r * N_ + cb) =
                            __halves2half2(q0, q1);
                        __half* qt = qTB + (long)bz * ((long)N_ * D_);
                        qt[(long)cb * D_ + r]       = q0;
                        qt[(long)(cb + 1) * D_ + r] = q1;
                    } else {
                        float bv2 = bias[r - 64];
                        long vo = (long)(r - 64) * N_ + cb;
                        *reinterpret_cast<__half2*>(Ch + cOff + vo) =
                            __floats2half2_rn(v0 + bv2, v1 + bv2);
                    }
                } else if (EPI == EPI_COLSCALE) {
                    float i0 = csb[cb - n0], i1 = csb[cb - n0 + 1];
                    const float* hb = hres + (long)bz * hresStride;
                    float2 h2 = *reinterpret_cast<const float2*>(hb + rowoff);
                    *reinterpret_cast<__half2*>(Ch + cOff + rowoff) =
                        __floats2half2_rn(h2.x - v0 * i0, h2.y - v1 * i1);
                } else { // EPI_T_UPDATE
                    v0 = fmaxf(fmaf(v0 + bsv, sc, sh), 0.f);
                    v1 = fmaxf(fmaf(v1 + bsv, sc, sh), 0.f);
                    const float* hb = hres + (long)bz * hresStride;
                    float2 h2 = *reinterpret_cast<const float2*>(hb + rowoff);
                    float o0 = v0 + h2.x, o1 = v1 + h2.y;
                    *reinterpret_cast<float2*>(Cf + cOff + rowoff) = make_float2(o0, o1);
                    float* ob = out2 + (long)bz * out2Stride;
                    *reinterpret_cast<float2*>(ob + rowoff) = make_float2(o0, o1);
                    const float* pb = posB + (long)bz * hresStride;
                    float2 p2 = *reinterpret_cast<const float2*>(pb + rowoff);
                    __half2* hb2 = reinterpret_cast<__half2*>(
                        hpOut + (long)bz * hresStride + rowoff);
                    *hb2 = __floats2half2_rn(o0 + p2.x, o1 + p2.y);
                }
            }
        }
    }
}

// ---------------------------------------------------------------------------
// rowstats: per (b, n) row, combine 16 tile stats -> s[n, t].
// ---------------------------------------------------------------------------
__global__ void __launch_bounds__(256)
rowstats_kernel(const float2* __restrict__ tstat, float* __restrict__ sarr)
{
    int idx = blockIdx.x * 256 + threadIdx.x;     // B*N = 16384 threads
    int b = idx >> 11, n = idx & 2047;
    float tm[NT_], ts[NT_];
    float rmax = -3.4e38f;
#pragma unroll
    for (int t = 0; t < NT_; t++) {
        float2 v = tstat[(((long)b * NT_ + t) << 11) + n];
        tm[t] = v.x; ts[t] = v.y;
        rmax = fmaxf(rmax, v.x);
    }
    float rsum = 0.f;
#pragma unroll
    for (int t = 0; t < NT_; t++) rsum += ts[t] * __expf(tm[t] - rmax);
    float rinv = 1.f / rsum;
#pragma unroll
    for (int t = 0; t < NT_; t++)
        sarr[(((long)b * NT_ + t) << 11) + n] = __expf(tm[t] - rmax) * rinv;
}

// ---------------------------------------------------------------------------
extern "C" void kernel_launch(void* const* d_in, const int* in_sizes, int n_in,
                              void* d_out, int out_size)
{
    (void)in_sizes; (void)n_in; (void)out_size;

    const float* x       = (const float*)d_in[0];
    const float* xyz     = (const float*)d_in[1];
    const float* conv1_w = (const float*)d_in[2];
    const float* convpos = (const float*)d_in[3];
    const float* bn1_g   = (const float*)d_in[4];
    const float* bn1_b   = (const float*)d_in[5];
    const float* bn1_m   = (const float*)d_in[6];
    const float* bn1_v   = (const float*)d_in[7];
    const float* Wqk     = (const float*)d_in[8];
    const float* Wv      = (const float*)d_in[9];
    const float* bv      = (const float*)d_in[10];
    const float* Wt      = (const float*)d_in[11];
    const float* bt      = (const float*)d_in[12];
    const float* bng     = (const float*)d_in[13];
    const float* bnb     = (const float*)d_in[14];
    const float* bnm     = (const float*)d_in[15];
    const float* bnv     = (const float*)d_in[16];
    float* out = (float*)d_out;

    float  *pos, *h0, *h1, *sarr;
    float2 *tstat;
    __half *hp, *xh, *q, *qT, *val, *dh, *ath, *wh;
    cudaGetSymbolAddress((void**)&pos,   g_pos);
    cudaGetSymbolAddress((void**)&h0,    g_h0);
    cudaGetSymbolAddress((void**)&h1,    g_h1);
    cudaGetSymbolAddress((void**)&hp,    g_hp);
    cudaGetSymbolAddress((void**)&xh,    g_xh);
    cudaGetSymbolAddress((void**)&q,     g_q);
    cudaGetSymbolAddress((void**)&qT,    g_qT);
    cudaGetSymbolAddress((void**)&val,   g_val);
    cudaGetSymbolAddress((void**)&dh,    g_dh);
    cudaGetSymbolAddress((void**)&ath,   g_ath);
    cudaGetSymbolAddress((void**)&wh,    g_wh);
    cudaGetSymbolAddress((void**)&tstat, g_tstat);
    cudaGetSymbolAddress((void**)&sarr,  g_s);

    cudaFuncSetAttribute(tgemm<EPI_BN_RELU>,  cudaFuncAttributeMaxDynamicSharedMemorySize, TG_SMEM);
    cudaFuncSetAttribute(tgemm<EPI_QVAL>,     cudaFuncAttributeMaxDynamicSharedMemorySize, TG_SMEM);
    cudaFuncSetAttribute(tgemm<EPI_EXPTILE>,  cudaFuncAttributeMaxDynamicSharedMemorySize, TG_SMEM);
    cudaFuncSetAttribute(tgemm<EPI_COLSCALE>, cudaFuncAttributeMaxDynamicSharedMemorySize, TG_SMEM);
    cudaFuncSetAttribute(tgemm<EPI_T_UPDATE>, cudaFuncAttributeMaxDynamicSharedMemorySize, TG_SMEM);

    const long SCN = (long)C_ * N_;
    const long SDN = (long)D_ * N_;
    const long SNN = (long)N_ * N_;
    const long SND = (long)N_ * D_;

    __half* w_conv1 = wh;
    __half* w_qv    = wh + SEG_W1;
    __half* w_t     = wh + SEG_W1 + SEG_QV;

    dim3 blk(256);
    dim3 gC (N_ / 128, 2, B_);        // M=256
    dim3 gQV(N_ / 128, 3, B_);        // M=320
    dim3 gE (N_ / 128, N_ / 128, B_); // M=N=2048

    prep_kernel<<<(int)((PREP_TOT + 255) / 256), blk>>>(conv1_w, Wqk, Wv, Wt, x,
                                                        convpos, xyz);

    // h0 = relu(bn1(conv1 @ x)); hp = half(h0 + pos)
    tgemm<EPI_BN_RELU><<<gC, blk, TG_SMEM>>>(
        w_conv1, 0, C_, C_, xh, SCN, h0, nullptr, SCN,
        nullptr, bn1_g, bn1_b, bn1_m, bn1_v,
        nullptr, SCN, pos, hp, nullptr, 0, nullptr, nullptr, nullptr, nullptr);

    float* hcur = h0;
    float* hnxt = h1;

    for (int i = 0; i < 4; i++) {
        // [q;val] = [Wqk;Wv] @ hp
        tgemm<EPI_QVAL><<<gQV, blk, TG_SMEM>>>(
            w_qv + (long)i * 81920, 0, 320, C_, hp, SCN, nullptr, val, SCN,
            bv + i * C_, nullptr, nullptr, nullptr, nullptr,
            nullptr, SCN, nullptr, nullptr, nullptr, 0, q, qT, nullptr, nullptr);

        // p~ = fp16(PSCALE * exp(E - tilemax)) + per-tile stats
        tgemm<EPI_EXPTILE><<<gE, blk, TG_SMEM>>>(
            qT, SND, N_, D_, q, SDN, nullptr, ath, SNN,
            nullptr, nullptr, nullptr, nullptr, nullptr,
            nullptr, SCN, nullptr, nullptr, nullptr, 0, nullptr, nullptr,
            tstat, nullptr);

        // s[n, t] = exp(tmax - rmax) / rsum
        rowstats_kernel<<<B_ * N_ / 256, blk>>>(tstat, sarr);

        // dh = half(h - (val @ (p~ . s)) / (PSCALE*1e-9 + colsum))
        tgemm<EPI_COLSCALE><<<gC, blk, TG_SMEM>>>(
            val, SCN, C_, N_, ath, SNN, nullptr, dh, SCN,
            nullptr, nullptr, nullptr, nullptr, nullptr,
            hcur, SCN, nullptr, nullptr, nullptr, 0, nullptr, nullptr,
            nullptr, sarr);

        // h_new = h + relu(bn(Wt @ dh + bt)); out slice; hp = half(h_new + pos)
        tgemm<EPI_T_UPDATE><<<gC, blk, TG_SMEM>>>(
            w_t + (long)i * C_ * C_, 0, C_, C_, dh, SCN, hnxt, nullptr, SCN,
            bt + i * C_, bng + i * C_, bnb + i * C_, bnm + i * C_, bnv + i * C_,
            hcur, SCN, pos, hp,
            out + (long)i * C_ * N_, (long)4 * C_ * N_, nullptr, nullptr,
            nullptr, nullptr);

        float* tmp = hcur; hcur = hnxt; hnxt = tmp;
    }
}

// round 12
// speedup vs baseline: 1.6777x; 1.0304x over previous
#include <cuda_runtime.h>
#include <cuda_fp16.h>
#include <cstdint>

// ---------------------------------------------------------------------------
// PCT position-embedding + 4 offset-attention SA layers. B=8, C=256, D=64,
// N=2048. fp16 mma.sync m16n8k16 (fp32 accum), PSCALE'd softmax probs.
// Softmax-free: energy GEMM emits p~ = PSCALE*exp(e - tilemax) fp16 + tile
// stats; rowstats -> s[n,t]; xr GEMM applies s in B fragments.
// h ping-pong removed: layer i+1 reads h from the output slice of layer i.
// pos stored fp16.
// ---------------------------------------------------------------------------

#define B_   8
#define C_   256
#define D_   64
#define N_   2048
#define PSCALE 32768.0f
#define NT_  16                       // N_/128 column tiles

__device__ __half g_pos[B_ * C_ * N_];
__device__ float  g_h0 [B_ * C_ * N_];
__device__ __half g_hp [B_ * C_ * N_];
__device__ __half g_xh [B_ * C_ * N_];
__device__ __half g_q  [B_ * D_ * N_];
__device__ __half g_qT [B_ * N_ * D_];
__device__ __half g_val[B_ * C_ * N_];
__device__ __half g_dh [B_ * C_ * N_];
__device__ __half g_ath[(long long)B_ * N_ * N_];   // p~ (fp16)
__device__ float2 g_tstat[B_ * NT_ * N_];           // {tilemax, tilesum}
__device__ float  g_s   [B_ * NT_ * N_];            // s[n,t]
__device__ __half g_wh [655360];

__device__ __forceinline__ uint32_t smem_u32(const void* p) {
    return (uint32_t)__cvta_generic_to_shared(p);
}
__device__ __forceinline__ uint32_t h2u(__half2 h) {
    return *reinterpret_cast<uint32_t*>(&h);
}

// ---------------------------------------------------------------------------
// warp-tile compute: 64x32 warp tile, fp16 m16n8k16, fp32 accum.
// SCALE variant multiplies B fragments by per-k fp32 scales from sst[32]
// and accumulates column sums of the scaled B into csumF[4].
// ---------------------------------------------------------------------------
template <bool SCALE>
__device__ __forceinline__ void compute_tile(
    const __half* __restrict__ Asb, const __half* __restrict__ Bsb,
    float acc[4][4][4], int lane, int wm0, int wn0,
    const float* __restrict__ sst, float* __restrict__ csumF)
{
    const int tg = lane & 3;
#pragma unroll
    for (int ks = 0; ks < 2; ks++) {
        uint32_t a[4][4];
#pragma unroll
        for (int mt = 0; mt < 4; mt++) {
            const __half* pa = Asb + (wm0 + mt * 16 + (lane & 15)) * 40
                             + ks * 16 + (lane >> 4) * 8;
            uint32_t ad = smem_u32(pa);
            asm volatile("ldmatrix.sync.aligned.m8n8.x4.shared.b16 {%0,%1,%2,%3}, [%4];"
                : "=r"(a[mt][0]), "=r"(a[mt][1]), "=r"(a[mt][2]), "=r"(a[mt][3])
                : "r"(ad));
        }
        uint32_t b[4][2];
#pragma unroll
        for (int j = 0; j < 2; j++) {
            const __half* pb = Bsb
                + (ks * 16 + (lane & 7) + ((lane >> 3) & 1) * 8) * 136
                + wn0 + j * 16 + (lane >> 4) * 8;
            uint32_t bd = smem_u32(pb);
            uint32_t r0, r1, r2, r3;
            asm volatile("ldmatrix.sync.aligned.m8n8.x4.trans.shared.b16 {%0,%1,%2,%3}, [%4];"
                : "=r"(r0), "=r"(r1), "=r"(r2), "=r"(r3) : "r"(bd));
            b[2 * j][0] = r0; b[2 * j][1] = r1;
            b[2 * j + 1][0] = r2; b[2 * j + 1][1] = r3;
        }
        if (SCALE) {
            // b[nt][0] holds k = ks*16 + 2tg,+1 ; b[nt][1] holds +8,+9
            float2 sA = *reinterpret_cast<const float2*>(&sst[ks * 16 + 2 * tg]);
            float2 sB = *reinterpret_cast<const float2*>(&sst[ks * 16 + 8 + 2 * tg]);
#pragma unroll
            for (int nt = 0; nt < 4; nt++) {
                __half2 h0v = *reinterpret_cast<__half2*>(&b[nt][0]);
                float2 f0 = __half22float2(h0v);
                f0.x *= sA.x; f0.y *= sA.y;
                b[nt][0] = h2u(__floats2half2_rn(f0.x, f0.y));
                __half2 h1v = *reinterpret_cast<__half2*>(&b[nt][1]);
                float2 f1 = __half22float2(h1v);
                f1.x *= sB.x; f1.y *= sB.y;
                b[nt][1] = h2u(__floats2half2_rn(f1.x, f1.y));
                csumF[nt] += (f0.x + f0.y) + (f1.x + f1.y);
            }
        }
#pragma unroll
        for (int mt = 0; mt < 4; mt++)
#pragma unroll
            for (int nt = 0; nt < 4; nt++) {
                asm volatile(
                    "mma.sync.aligned.m16n8k16.row.col.f32.f16.f16.f32 "
                    "{%0,%1,%2,%3}, {%4,%5,%6,%7}, {%8,%9}, {%0,%1,%2,%3};"
                    : "+f"(acc[mt][nt][0]), "+f"(acc[mt][nt][1]),
                      "+f"(acc[mt][nt][2]), "+f"(acc[mt][nt][3])
                    : "r"(a[mt][0]), "r"(a[mt][1]), "r"(a[mt][2]), "r"(a[mt][3]),
                      "r"(b[nt][0]), "r"(b[nt][1]));
            }
    }
}

// ---------------------------------------------------------------------------
// prep kernel: weights + x to fp16, pos (fp16).
// ---------------------------------------------------------------------------
#define SEG_W1   65536L
#define SEG_QV   327680L
#define SEG_WT   262144L
#define SEG_X    ((long)B_ * C_ * N_)
#define PREP_TOT (SEG_W1 + SEG_QV + SEG_WT + SEG_X + SEG_X)

__global__ void prep_kernel(const float* __restrict__ conv1_w,
                            const float* __restrict__ Wqk,
                            const float* __restrict__ Wv,
                            const float* __restrict__ Wt,
                            const float* __restrict__ x,
                            const float* __restrict__ convpos,
                            const float* __restrict__ xyz)
{
    long i = (long)blockIdx.x * 256 + threadIdx.x;
    if (i >= PREP_TOT) return;
    if (i < SEG_W1) {
        g_wh[i] = __float2half_rn(conv1_w[i]);
    } else if (i < SEG_W1 + SEG_QV) {
        long j = i - SEG_W1;
        int layer = (int)(j / 81920);
        long o = j % 81920;
        float v = (o < 16384) ? Wqk[(long)layer * 16384 + o]
                              : Wv[(long)layer * 65536 + (o - 16384)];
        g_wh[i] = __float2half_rn(v);
    } else if (i < SEG_W1 + SEG_QV + SEG_WT) {
        g_wh[i] = __float2half_rn(Wt[i - SEG_W1 - SEG_QV]);
    } else if (i < SEG_W1 + SEG_QV + SEG_WT + SEG_X) {
        long j = i - SEG_W1 - SEG_QV - SEG_WT;
        g_xh[j] = __float2half_rn(x[j]);
    } else {
        long j = i - SEG_W1 - SEG_QV - SEG_WT - SEG_X;
        int n = (int)(j % N_);
        int c = (int)((j / N_) % C_);
        int b = (int)(j / ((long)C_ * N_));
        const float* pp = xyz + ((long)b * N_ + n) * 3;
        g_pos[j] = __float2half_rn(
            convpos[c * 3 + 0] * pp[0] + convpos[c * 3 + 1] * pp[1]
            + convpos[c * 3 + 2] * pp[2]);
    }
}

// ---------------------------------------------------------------------------
// fp16 GEMM, block tile 128x128, 4-stage cp.async ring, 1 barrier/stage.
// ---------------------------------------------------------------------------
enum { EPI_BN_RELU = 0, EPI_QVAL = 1, EPI_EXPTILE = 2, EPI_COLSCALE = 3,
       EPI_T_UPDATE = 4 };

#define TG_STAGES   4
#define TG_AS_STR   (128 * 40)
#define TG_BS_STR   (32 * 136)
#define TG_RING_B   (TG_STAGES * (TG_AS_STR + TG_BS_STR) * 2)
#define TG_CS_B     (TG_RING_B)
#define TG_CSB_B    (TG_CS_B + 16 * 128 * 4)
#define TG_SR_B     (TG_CSB_B + 128 * 4)
#define TG_SMEM     (TG_SR_B + TG_STAGES * 32 * 4)

#define SCN_ ((long)C_ * N_)

template <int EPI>
__global__ void __launch_bounds__(256, 2)
tgemm(const __half* __restrict__ A, long aStride, int M, int K,
      const __half* __restrict__ Bm, long bStride,
      float* __restrict__ Cf, __half* __restrict__ Ch, long cStride,
      const float* __restrict__ bias,
      const float* __restrict__ bng, const float* __restrict__ bnb,
      const float* __restrict__ bnm, const float* __restrict__ bnv,
      const float* __restrict__ hres, long hresStride,
      const __half* __restrict__ posB,
      __half* __restrict__ hpOut,
      float* __restrict__ out2, long out2Stride,
      __half* __restrict__ qB, __half* __restrict__ qTB,
      float2* __restrict__ tstatOut, const float* __restrict__ sArr)
{
    extern __shared__ char smd[];
    __half* AsBase = reinterpret_cast<__half*>(smd);
    __half* BsBase = AsBase + TG_STAGES * TG_AS_STR;
    float (*red4)[4] = reinterpret_cast<float(*)[4]>(smd + TG_CS_B);
    float* csb   = reinterpret_cast<float*>(smd + TG_CSB_B);
    float* sring = reinterpret_cast<float*>(smd + TG_SR_B);

    const int bz = blockIdx.z;
    const __half* Ab = A + (long)bz * aStride;
    const __half* Bb = Bm + (long)bz * bStride;
    const float* sBase = (EPI == EPI_COLSCALE)
        ? (sArr + (((long)bz * NT_ + blockIdx.x) << 11)) : nullptr;

    const int m0 = blockIdx.y * 128;
    const int n0 = blockIdx.x * 128;
    const int t  = threadIdx.x;
    const int lane = t & 31;
    const int w    = t >> 5;
    const int g  = lane >> 2, tg = lane & 3;
    const int wm0 = (w >> 2) * 64, wn0 = (w & 3) * 32;

    float acc[4][4][4];
#pragma unroll
    for (int i = 0; i < 4; i++)
#pragma unroll
        for (int j = 0; j < 4; j++)
#pragma unroll
            for (int k = 0; k < 4; k++) acc[i][j][k] = 0.f;

    float csumF[4] = {0.f, 0.f, 0.f, 0.f};

    const int aRow = t >> 2, aCg = (t & 3) * 8;
    const int bRow = t >> 4, bCg = (t & 15) * 8;
    const int nStages = K >> 5;

    // prologue
#pragma unroll
    for (int s = 0; s < TG_STAGES - 1; s++) {
        if (s < nStages) {
            const int k0 = s * 32;
            __half* As = AsBase + s * TG_AS_STR;
            __half* Bs = BsBase + s * TG_BS_STR;
#pragma unroll
            for (int h = 0; h < 2; h++) {
                int row = aRow + h * 64;
                if (m0 + row < M) {
                    uint32_t dst = smem_u32(As + row * 40 + aCg);
                    const __half* src = Ab + (long)(m0 + row) * K + k0 + aCg;
                    asm volatile("cp.async.cg.shared.global [%0], [%1], 16;" :: "r"(dst), "l"(src));
                }
            }
#pragma unroll
            for (int h = 0; h < 2; h++) {
                int row = bRow + h * 16;
                uint32_t dst = smem_u32(Bs + row * 136 + bCg);
                const __half* src = Bb + (long)(k0 + row) * N_ + n0 + bCg;
                asm volatile("cp.async.cg.shared.global [%0], [%1], 16;" :: "r"(dst), "l"(src));
            }
            if (EPI == EPI_COLSCALE && t < 8) {
                uint32_t dst = smem_u32(sring + s * 32 + t * 4);
                const float* src = sBase + k0 + t * 4;
                asm volatile("cp.async.cg.shared.global [%0], [%1], 16;" :: "r"(dst), "l"(src));
            }
        }
        asm volatile("cp.async.commit_group;");
    }

    for (int s = 0; s < nStages; s++) {
        const int buf = s & (TG_STAGES - 1);
        asm volatile("cp.async.wait_group %0;" :: "n"(TG_STAGES - 2));
        __syncthreads();

        const int sn = s + TG_STAGES - 1;
        if (sn < nStages) {
            const int k0 = sn * 32, nb = sn & (TG_STAGES - 1);
            __half* As = AsBase + nb * TG_AS_STR;
            __half* Bs = BsBase + nb * TG_BS_STR;
#pragma unroll
            for (int h = 0; h < 2; h++) {
                int row = aRow + h * 64;
                if (m0 + row < M) {
                    uint32_t dst = smem_u32(As + row * 40 + aCg);
                    const __half* src = Ab + (long)(m0 + row) * K + k0 + aCg;
                    asm volatile("cp.async.cg.shared.global [%0], [%1], 16;" :: "r"(dst), "l"(src));
                }
            }
#pragma unroll
            for (int h = 0; h < 2; h++) {
                int row = bRow + h * 16;
                uint32_t dst = smem_u32(Bs + row * 136 + bCg);
                const __half* src = Bb + (long)(k0 + row) * N_ + n0 + bCg;
                asm volatile("cp.async.cg.shared.global [%0], [%1], 16;" :: "r"(dst), "l"(src));
            }
            if (EPI == EPI_COLSCALE && t < 8) {
                uint32_t dst = smem_u32(sring + nb * 32 + t * 4);
                const float* src = sBase + k0 + t * 4;
                asm volatile("cp.async.cg.shared.global [%0], [%1], 16;" :: "r"(dst), "l"(src));
            }
        }
        asm volatile("cp.async.commit_group;");

        const __half* AsC = AsBase + buf * TG_AS_STR;
        const __half* BsC = BsBase + buf * TG_BS_STR;
        compute_tile<EPI == EPI_COLSCALE>(AsC, BsC, acc, lane, wm0, wn0,
                                          sring + buf * 32, csumF);
    }

    const long cOff = (long)bz * cStride;

    // ------- EXPTILE epilogue -------
    if (EPI == EPI_EXPTILE) {
        __syncthreads();
        float tmaxv[4][2];
#pragma unroll
        for (int mt = 0; mt < 4; mt++)
#pragma unroll
            for (int hf = 0; hf < 2; hf++) {
                float mval = -3.4e38f;
#pragma unroll
                for (int nt = 0; nt < 4; nt++) {
                    mval = fmaxf(mval, acc[mt][nt][hf * 2 + 0]);
                    mval = fmaxf(mval, acc[mt][nt][hf * 2 + 1]);
                }
                mval = fmaxf(mval, __shfl_xor_sync(0xffffffffu, mval, 1));
                mval = fmaxf(mval, __shfl_xor_sync(0xffffffffu, mval, 2));
                tmaxv[mt][hf] = mval;
            }
        if (tg == 0) {
#pragma unroll
            for (int mt = 0; mt < 4; mt++)
#pragma unroll
                for (int hf = 0; hf < 2; hf++)
                    red4[wm0 + mt * 16 + g + hf * 8][w & 3] = tmaxv[mt][hf];
        }
        __syncthreads();
#pragma unroll
        for (int mt = 0; mt < 4; mt++)
#pragma unroll
            for (int hf = 0; hf < 2; hf++) {
                const float* rr = red4[wm0 + mt * 16 + g + hf * 8];
                tmaxv[mt][hf] = fmaxf(fmaxf(rr[0], rr[1]), fmaxf(rr[2], rr[3]));
            }
        __syncthreads();
        float psum[4][2];
#pragma unroll
        for (int mt = 0; mt < 4; mt++)
#pragma unroll
            for (int hf = 0; hf < 2; hf++) {
                float s2 = 0.f;
#pragma unroll
                for (int nt = 0; nt < 4; nt++) {
                    float e0 = __expf(acc[mt][nt][hf * 2 + 0] - tmaxv[mt][hf]);
                    float e1 = __expf(acc[mt][nt][hf * 2 + 1] - tmaxv[mt][hf]);
                    acc[mt][nt][hf * 2 + 0] = e0;
                    acc[mt][nt][hf * 2 + 1] = e1;
                    s2 += e0 + e1;
                }
                s2 += __shfl_xor_sync(0xffffffffu, s2, 1);
                s2 += __shfl_xor_sync(0xffffffffu, s2, 2);
                psum[mt][hf] = s2;
            }
        if (tg == 0) {
#pragma unroll
            for (int mt = 0; mt < 4; mt++)
#pragma unroll
                for (int hf = 0; hf < 2; hf++)
                    red4[wm0 + mt * 16 + g + hf * 8][w & 3] = psum[mt][hf];
        }
        __syncthreads();
#pragma unroll
        for (int mt = 0; mt < 4; mt++)
#pragma unroll
            for (int hf = 0; hf < 2; hf++) {
                const int rl = wm0 + mt * 16 + g + hf * 8;
                const int r = m0 + rl;
#pragma unroll
                for (int nt = 0; nt < 4; nt++) {
                    const int cb = n0 + wn0 + nt * 8 + 2 * tg;
                    *reinterpret_cast<__half2*>(Ch + cOff + (long)r * N_ + cb) =
                        __floats2half2_rn(PSCALE * acc[mt][nt][hf * 2 + 0],
                                          PSCALE * acc[mt][nt][hf * 2 + 1]);
                }
                if ((w & 3) == 0 && tg == 0) {
                    const float* rr = red4[rl];
                    tstatOut[(((long)bz * NT_ + blockIdx.x) << 11) + r] =
                        make_float2(tmaxv[mt][hf], rr[0] + rr[1] + rr[2] + rr[3]);
                }
            }
        return;
    }

    if (EPI == EPI_COLSCALE) {
        __syncthreads();
#pragma unroll
        for (int nt = 0; nt < 4; nt++) {
            csumF[nt] += __shfl_xor_sync(0xffffffffu, csumF[nt], 1);
            csumF[nt] += __shfl_xor_sync(0xffffffffu, csumF[nt], 2);
        }
        if (w < 4 && tg == 0) {
#pragma unroll
            for (int nt = 0; nt < 4; nt++)
                csb[wn0 + nt * 8 + g] = 1.f / (PSCALE * 1e-9f + csumF[nt]);
        }
        __syncthreads();
    }

#pragma unroll
    for (int mt = 0; mt < 4; mt++) {
#pragma unroll
        for (int half_ = 0; half_ < 2; half_++) {
            const int r = m0 + wm0 + mt * 16 + g + half_ * 8;
            if (r >= M) continue;

            float sc = 1.f, sh = 0.f, bsv = 0.f;
            if (EPI == EPI_BN_RELU || EPI == EPI_T_UPDATE) {
                float inv = rsqrtf(bnv[r] + 1e-5f);
                sc = bng[r] * inv; sh = bnb[r] - bnm[r] * sc;
            }
            if (EPI == EPI_T_UPDATE) bsv = bias[r];

#pragma unroll
            for (int nt = 0; nt < 4; nt++) {
                const int cb = n0 + wn0 + nt * 8 + 2 * tg;
                float v0 = acc[mt][nt][half_ * 2 + 0];
                float v1 = acc[mt][nt][half_ * 2 + 1];
                long rowoff = (long)r * N_ + cb;

                if (EPI == EPI_BN_RELU) {
                    v0 = fmaxf(fmaf(v0, sc, sh), 0.f);
                    v1 = fmaxf(fmaf(v1, sc, sh), 0.f);
                    *reinterpret_cast<float2*>(Cf + cOff + rowoff) = make_float2(v0, v1);
                    const __half* pb = posB + (long)bz * SCN_;
                    float2 p2 = __half22float2(
                        *reinterpret_cast<const __half2*>(pb + rowoff));
                    __half2* hbp = reinterpret_cast<__half2*>(
                        hpOut + (long)bz * SCN_ + rowoff);
                    *hbp = __floats2half2_rn(v0 + p2.x, v1 + p2.y);
                } else if (EPI == EPI_QVAL) {
                    if (r < 64) {
                        __half q0 = __float2half_rn(v0), q1 = __float2half_rn(v1);
                        __half* qb = qB + (long)bz * ((long)D_ * N_);
                        *reinterpret_cast<__half2*>(qb + (long)r * N_ + cb) =
                            __halves2half2(q0, q1);
                        __half* qt = qTB + (long)bz * ((long)N_ * D_);
                        qt[(long)cb * D_ + r]       = q0;
                        qt[(long)(cb + 1) * D_ + r] = q1;
                    } else {
                        float bv2 = bias[r - 64];
                        long vo = (long)(r - 64) * N_ + cb;
                        *reinterpret_cast<__half2*>(Ch + cOff + vo) =
                            __floats2half2_rn(v0 + bv2, v1 + bv2);
                    }
                } else if (EPI == EPI_COLSCALE) {
                    float i0 = csb[cb - n0], i1 = csb[cb - n0 + 1];
                    const float* hb = hres + (long)bz * hresStride;
                    float2 h2 = *reinterpret_cast<const float2*>(hb + rowoff);
                    *reinterpret_cast<__half2*>(Ch + cOff + rowoff) =
                        __floats2half2_rn(h2.x - v0 * i0, h2.y - v1 * i1);
                } else { // EPI_T_UPDATE
                    v0 = fmaxf(fmaf(v0 + bsv, sc, sh), 0.f);
                    v1 = fmaxf(fmaf(v1 + bsv, sc, sh), 0.f);
                    const float* hb = hres + (long)bz * hresStride;
                    float2 h2 = *reinterpret_cast<const float2*>(hb + rowoff);
                    float o0 = v0 + h2.x, o1 = v1 + h2.y;
                    float* ob = out2 + (long)bz * out2Stride;
                    *reinterpret_cast<float2*>(ob + rowoff) = make_float2(o0, o1);
                    if (hpOut) {
                        const __half* pb = posB + (long)bz * SCN_;
                        float2 p2 = __half22float2(
                            *reinterpret_cast<const __half2*>(pb + rowoff));
                        __half2* hb2 = reinterpret_cast<__half2*>(
                            hpOut + (long)bz * SCN_ + rowoff);
                        *hb2 = __floats2half2_rn(o0 + p2.x, o1 + p2.y);
                    }
                }
            }
        }
    }
}

// ---------------------------------------------------------------------------
// rowstats: per (b, n) row, combine 16 tile stats -> s[n, t].
// ---------------------------------------------------------------------------
__global__ void __launch_bounds__(256)
rowstats_kernel(const float2* __restrict__ tstat, float* __restrict__ sarr)
{
    int idx = blockIdx.x * 256 + threadIdx.x;
    int b = idx >> 11, n = idx & 2047;
    float tm[NT_], ts[NT_];
    float rmax = -3.4e38f;
#pragma unroll
    for (int t = 0; t < NT_; t++) {
        float2 v = tstat[(((long)b * NT_ + t) << 11) + n];
        tm[t] = v.x; ts[t] = v.y;
        rmax = fmaxf(rmax, v.x);
    }
    float rsum = 0.f;
#pragma unroll
    for (int t = 0; t < NT_; t++) rsum += ts[t] * __expf(tm[t] - rmax);
    float rinv = 1.f / rsum;
#pragma unroll
    for (int t = 0; t < NT_; t++)
        sarr[(((long)b * NT_ + t) << 11) + n] = __expf(tm[t] - rmax) * rinv;
}

// ---------------------------------------------------------------------------
extern "C" void kernel_launch(void* const* d_in, const int* in_sizes, int n_in,
                              void* d_out, int out_size)
{
    (void)in_sizes; (void)n_in; (void)out_size;

    const float* x       = (const float*)d_in[0];
    const float* xyz     = (const float*)d_in[1];
    const float* conv1_w = (const float*)d_in[2];
    const float* convpos = (const float*)d_in[3];
    const float* bn1_g   = (const float*)d_in[4];
    const float* bn1_b   = (const float*)d_in[5];
    const float* bn1_m   = (const float*)d_in[6];
    const float* bn1_v   = (const float*)d_in[7];
    const float* Wqk     = (const float*)d_in[8];
    const float* Wv      = (const float*)d_in[9];
    const float* bv      = (const float*)d_in[10];
    const float* Wt      = (const float*)d_in[11];
    const float* bt      = (const float*)d_in[12];
    const float* bng     = (const float*)d_in[13];
    const float* bnb     = (const float*)d_in[14];
    const float* bnm     = (const float*)d_in[15];
    const float* bnv     = (const float*)d_in[16];
    float* out = (float*)d_out;

    float  *h0, *sarr;
    float2 *tstat;
    __half *pos, *hp, *xh, *q, *qT, *val, *dh, *ath, *wh;
    cudaGetSymbolAddress((void**)&pos,   g_pos);
    cudaGetSymbolAddress((void**)&h0,    g_h0);
    cudaGetSymbolAddress((void**)&hp,    g_hp);
    cudaGetSymbolAddress((void**)&xh,    g_xh);
    cudaGetSymbolAddress((void**)&q,     g_q);
    cudaGetSymbolAddress((void**)&qT,    g_qT);
    cudaGetSymbolAddress((void**)&val,   g_val);
    cudaGetSymbolAddress((void**)&dh,    g_dh);
    cudaGetSymbolAddress((void**)&ath,   g_ath);
    cudaGetSymbolAddress((void**)&wh,    g_wh);
    cudaGetSymbolAddress((void**)&tstat, g_tstat);
    cudaGetSymbolAddress((void**)&sarr,  g_s);

    cudaFuncSetAttribute(tgemm<EPI_BN_RELU>,  cudaFuncAttributeMaxDynamicSharedMemorySize, TG_SMEM);
    cudaFuncSetAttribute(tgemm<EPI_QVAL>,     cudaFuncAttributeMaxDynamicSharedMemorySize, TG_SMEM);
    cudaFuncSetAttribute(tgemm<EPI_EXPTILE>,  cudaFuncAttributeMaxDynamicSharedMemorySize, TG_SMEM);
    cudaFuncSetAttribute(tgemm<EPI_COLSCALE>, cudaFuncAttributeMaxDynamicSharedMemorySize, TG_SMEM);
    cudaFuncSetAttribute(tgemm<EPI_T_UPDATE>, cudaFuncAttributeMaxDynamicSharedMemorySize, TG_SMEM);

    const long SCN = (long)C_ * N_;
    const long SDN = (long)D_ * N_;
    const long SNN = (long)N_ * N_;
    const long SND = (long)N_ * D_;
    const long SOUT = (long)4 * C_ * N_;

    __half* w_conv1 = wh;
    __half* w_qv    = wh + SEG_W1;
    __half* w_t     = wh + SEG_W1 + SEG_QV;

    dim3 blk(256);
    dim3 gC (N_ / 128, 2, B_);
    dim3 gQV(N_ / 128, 3, B_);
    dim3 gE (N_ / 128, N_ / 128, B_);

    prep_kernel<<<(int)((PREP_TOT + 255) / 256), blk>>>(conv1_w, Wqk, Wv, Wt, x,
                                                        convpos, xyz);

    // h0 = relu(bn1(conv1 @ x)); hp = half(h0 + pos)
    tgemm<EPI_BN_RELU><<<gC, blk, TG_SMEM>>>(
        w_conv1, 0, C_, C_, xh, SCN, h0, nullptr, SCN,
        nullptr, bn1_g, bn1_b, bn1_m, bn1_v,
        nullptr, SCN, pos, hp, nullptr, 0, nullptr, nullptr, nullptr, nullptr);

    const float* hbase = h0;   // current h tensor (read-only)
    long hstride = SCN;

    for (int i = 0; i < 4; i++) {
        // [q;val] = [Wqk;Wv] @ hp
        tgemm<EPI_QVAL><<<gQV, blk, TG_SMEM>>>(
            w_qv + (long)i * 81920, 0, 320, C_, hp, SCN, nullptr, val, SCN,
            bv + i * C_, nullptr, nullptr, nullptr, nullptr,
            nullptr, SCN, nullptr, nullptr, nullptr, 0, q, qT, nullptr, nullptr);

        // p~ = fp16(PSCALE * exp(E - tilemax)) + per-tile stats
        tgemm<EPI_EXPTILE><<<gE, blk, TG_SMEM>>>(
            qT, SND, N_, D_, q, SDN, nullptr, ath, SNN,
            nullptr, nullptr, nullptr, nullptr, nullptr,
            nullptr, SCN, nullptr, nullptr, nullptr, 0, nullptr, nullptr,
            tstat, nullptr);

        // s[n, t] = exp(tmax - rmax) / rsum
        rowstats_kernel<<<B_ * N_ / 256, blk>>>(tstat, sarr);

        // dh = half(h - (val @ (p~ . s)) / (PSCALE*1e-9 + colsum))
        tgemm<EPI_COLSCALE><<<gC, blk, TG_SMEM>>>(
            val, SCN, C_, N_, ath, SNN, nullptr, dh, SCN,
            nullptr, nullptr, nullptr, nullptr, nullptr,
            hbase, hstride, nullptr, nullptr, nullptr, 0, nullptr, nullptr,
            nullptr, sarr);

        // out[i] = h + relu(bn(Wt @ dh + bt)); hp = half(out[i] + pos) if i<3
        tgemm<EPI_T_UPDATE><<<gC, blk, TG_SMEM>>>(
            w_t + (long)i * C_ * C_, 0, C_, C_, dh, SCN, nullptr, nullptr, 0,
            bt + i * C_, bng + i * C_, bnb + i * C_, bnm + i * C_, bnv + i * C_,
            hbase, hstride, pos, (i < 3) ? hp : nullptr,
            out + (long)i * C_ * N_, SOUT, nullptr, nullptr,
            nullptr, nullptr);

        hbase = out + (long)i * C_ * N_;
        hstride = SOUT;
    }
}